// round 1
// baseline (speedup 1.0000x reference)
#include <cuda_runtime.h>
#include <cstdint>

#define D_MODEL 128
#define N_SEQ   2048
#define BATCH   4
#define N_HEAD  8
#define D_K     16
#define NEG_INF -1e30f

// Scratch (device globals — no allocations allowed)
__device__ float g_q[BATCH * N_SEQ * D_MODEL];
__device__ float g_k[BATCH * N_SEQ * D_MODEL];
__device__ float g_v[BATCH * N_SEQ * D_MODEL];
__device__ float g_attn[BATCH * N_SEQ * D_MODEL];

// ---------------------------------------------------------------------------
// Kernel 1: QKV projection.
// x: (B, D, N)   q/k/v: (B, N, D)
// q[b,n,j] = sum_d x[b,d,n] * Wq[j,d] + bq[j]
// CTA = (n-tile of 64, b). 256 threads. Tiles: Xs[d][m] 128x64, Wt[d][j] 128x132 (padded).
// ---------------------------------------------------------------------------
__global__ __launch_bounds__(256) void qkv_proj_kernel(
    const float* __restrict__ x,
    const float* __restrict__ Wq, const float* __restrict__ bq,
    const float* __restrict__ Wk, const float* __restrict__ bk,
    const float* __restrict__ Wv, const float* __restrict__ bv)
{
    extern __shared__ float sm[];
    float* Xs = sm;              // [128][64]  = 8192 floats
    float* Wt = sm + 8192;       // [128][132] = 16896 floats (pad for bank conflicts)

    const int b  = blockIdx.y;
    const int n0 = blockIdx.x * 64;
    const int tid = threadIdx.x;

    // Load X tile: Xs[d*64+m] = x[b, d, n0+m]  (coalesced in m)
#pragma unroll
    for (int it = 0; it < 32; ++it) {
        int i = tid + it * 256;
        int d = i >> 6, m = i & 63;
        Xs[i] = x[((size_t)b * D_MODEL + d) * N_SEQ + n0 + m];
    }

    const float* Ws[3]; Ws[0] = Wq; Ws[1] = Wk; Ws[2] = Wv;
    const float* Bs[3]; Bs[0] = bq; Bs[1] = bk; Bs[2] = bv;
    float* Os[3];       Os[0] = g_q; Os[1] = g_k; Os[2] = g_v;

    const int tx = tid & 15;   // m group: m = tx*4 .. +3
    const int ty = tid >> 4;   // j group: j = ty*8 .. +7

#pragma unroll 1
    for (int w = 0; w < 3; ++w) {
        __syncthreads();
        // Load W transposed: Wt[d*132 + j] = W[j*128 + d] (coalesced global reads)
#pragma unroll
        for (int it = 0; it < 64; ++it) {
            int i = tid + it * 256;
            int j = i >> 7, d = i & 127;
            Wt[d * 132 + j] = Ws[w][i];
        }
        __syncthreads();

        float c[4][8];
#pragma unroll
        for (int mm = 0; mm < 4; ++mm)
#pragma unroll
            for (int jj = 0; jj < 8; ++jj) c[mm][jj] = 0.f;

#pragma unroll 4
        for (int d = 0; d < 128; ++d) {
            float4 xv = *(const float4*)&Xs[d * 64 + tx * 4];
            float4 wa = *(const float4*)&Wt[d * 132 + ty * 8];
            float4 wb = *(const float4*)&Wt[d * 132 + ty * 8 + 4];
            float xs[4] = {xv.x, xv.y, xv.z, xv.w};
            float ws[8] = {wa.x, wa.y, wa.z, wa.w, wb.x, wb.y, wb.z, wb.w};
#pragma unroll
            for (int mm = 0; mm < 4; ++mm)
#pragma unroll
                for (int jj = 0; jj < 8; ++jj)
                    c[mm][jj] = fmaf(xs[mm], ws[jj], c[mm][jj]);
        }

        float bias[8];
#pragma unroll
        for (int jj = 0; jj < 8; ++jj) bias[jj] = Bs[w][ty * 8 + jj];

        float* outp = Os[w];
#pragma unroll
        for (int mm = 0; mm < 4; ++mm) {
            size_t base = ((size_t)b * N_SEQ + n0 + tx * 4 + mm) * D_MODEL + ty * 8;
            float4 o0 = {c[mm][0] + bias[0], c[mm][1] + bias[1], c[mm][2] + bias[2], c[mm][3] + bias[3]};
            float4 o1 = {c[mm][4] + bias[4], c[mm][5] + bias[5], c[mm][6] + bias[6], c[mm][7] + bias[7]};
            *(float4*)&outp[base]     = o0;
            *(float4*)&outp[base + 4] = o1;
        }
    }
}

// ---------------------------------------------------------------------------
// Kernel 2: flash attention.
// Grid (16 q-tiles, 8 heads, 4 batch), 128 threads; each thread owns ONE q row.
// Online softmax with 32-score chunks kept in registers.
// ---------------------------------------------------------------------------
__global__ __launch_bounds__(128) void flash_attn_kernel(
    const float* __restrict__ mask)
{
    __shared__ float Ks[128 * 16];
    __shared__ float Vs[128 * 16];
    __shared__ float Ms[128];

    const int qt = blockIdx.x, h = blockIdx.y, b = blockIdx.z;
    const int tid = threadIdx.x;
    const int n = qt * 128 + tid;

    const float scale = 0.08838834764831843f;  // 1/sqrt(128)

    // Load this thread's q row, pre-scaled
    const float* qp = g_q + ((size_t)b * N_SEQ + n) * D_MODEL + h * D_K;
    float4 q0 = *(const float4*)&qp[0];
    float4 q1 = *(const float4*)&qp[4];
    float4 q2 = *(const float4*)&qp[8];
    float4 q3 = *(const float4*)&qp[12];
    q0.x *= scale; q0.y *= scale; q0.z *= scale; q0.w *= scale;
    q1.x *= scale; q1.y *= scale; q1.z *= scale; q1.w *= scale;
    q2.x *= scale; q2.y *= scale; q2.z *= scale; q2.w *= scale;
    q3.x *= scale; q3.y *= scale; q3.z *= scale; q3.w *= scale;

    float acc[16];
#pragma unroll
    for (int d = 0; d < 16; ++d) acc[d] = 0.f;
    float m_run = -1e30f, l = 0.f;

#pragma unroll 1
    for (int t = 0; t < 16; ++t) {
        const int kv0 = t * 128;
        // Load K/V tile rows (thread tid loads row tid) + mask
        {
            const float* kp = g_k + ((size_t)b * N_SEQ + kv0 + tid) * D_MODEL + h * D_K;
            const float* vp = g_v + ((size_t)b * N_SEQ + kv0 + tid) * D_MODEL + h * D_K;
            float4* kd = (float4*)&Ks[tid * 16];
            float4* vd = (float4*)&Vs[tid * 16];
            kd[0] = *(const float4*)&kp[0];  kd[1] = *(const float4*)&kp[4];
            kd[2] = *(const float4*)&kp[8];  kd[3] = *(const float4*)&kp[12];
            vd[0] = *(const float4*)&vp[0];  vd[1] = *(const float4*)&vp[4];
            vd[2] = *(const float4*)&vp[8];  vd[3] = *(const float4*)&vp[12];
            Ms[tid] = mask[(size_t)b * N_SEQ + kv0 + tid];
        }
        __syncthreads();

#pragma unroll 1
        for (int c = 0; c < 4; ++c) {
            float s[32];
            float cmax = -1e30f;
#pragma unroll
            for (int jj = 0; jj < 32; ++jj) {
                const int j = c * 32 + jj;
                const float4* kr = (const float4*)&Ks[j * 16];
                float4 k0 = kr[0], k1 = kr[1], k2 = kr[2], k3 = kr[3];
                float dot = q0.x * k0.x + q0.y * k0.y + q0.z * k0.z + q0.w * k0.w
                          + q1.x * k1.x + q1.y * k1.y + q1.z * k1.z + q1.w * k1.w
                          + q2.x * k2.x + q2.y * k2.y + q2.z * k2.z + q2.w * k2.w
                          + q3.x * k3.x + q3.y * k3.y + q3.z * k3.z + q3.w * k3.w;
                const float mj = Ms[j];
                const float sv = dot * mj + (1.f - mj) * NEG_INF;
                s[jj] = sv;
                cmax = fmaxf(cmax, sv);
            }
            const float m_new = fmaxf(m_run, cmax);
            const float corr = __expf(m_run - m_new);
            l *= corr;
#pragma unroll
            for (int d = 0; d < 16; ++d) acc[d] *= corr;
#pragma unroll
            for (int jj = 0; jj < 32; ++jj) {
                const int j = c * 32 + jj;
                const float p = __expf(s[jj] - m_new);
                l += p;
                const float4* vr = (const float4*)&Vs[j * 16];
                float4 v0 = vr[0], v1 = vr[1], v2 = vr[2], v3 = vr[3];
                acc[0]  = fmaf(p, v0.x, acc[0]);  acc[1]  = fmaf(p, v0.y, acc[1]);
                acc[2]  = fmaf(p, v0.z, acc[2]);  acc[3]  = fmaf(p, v0.w, acc[3]);
                acc[4]  = fmaf(p, v1.x, acc[4]);  acc[5]  = fmaf(p, v1.y, acc[5]);
                acc[6]  = fmaf(p, v1.z, acc[6]);  acc[7]  = fmaf(p, v1.w, acc[7]);
                acc[8]  = fmaf(p, v2.x, acc[8]);  acc[9]  = fmaf(p, v2.y, acc[9]);
                acc[10] = fmaf(p, v2.z, acc[10]); acc[11] = fmaf(p, v2.w, acc[11]);
                acc[12] = fmaf(p, v3.x, acc[12]); acc[13] = fmaf(p, v3.y, acc[13]);
                acc[14] = fmaf(p, v3.z, acc[14]); acc[15] = fmaf(p, v3.w, acc[15]);
            }
            m_run = m_new;
        }
        __syncthreads();
    }

    const float inv = 1.f / l;
    float* op = g_attn + ((size_t)b * N_SEQ + n) * D_MODEL + h * D_K;
    float4 o0 = {acc[0] * inv,  acc[1] * inv,  acc[2] * inv,  acc[3] * inv};
    float4 o1 = {acc[4] * inv,  acc[5] * inv,  acc[6] * inv,  acc[7] * inv};
    float4 o2 = {acc[8] * inv,  acc[9] * inv,  acc[10] * inv, acc[11] * inv};
    float4 o3 = {acc[12] * inv, acc[13] * inv, acc[14] * inv, acc[15] * inv};
    *(float4*)&op[0]  = o0; *(float4*)&op[4]  = o1;
    *(float4*)&op[8]  = o2; *(float4*)&op[12] = o3;
}

// ---------------------------------------------------------------------------
// Kernel 3: FC projection + output transpose.
// out[b, j, n] = sum_d attn[b, n, d] * Wfc[j, d] + bfc[j]     out: (B, D, N)
// ---------------------------------------------------------------------------
__global__ __launch_bounds__(256) void fc_proj_kernel(
    const float* __restrict__ Wfc, const float* __restrict__ bfc,
    float* __restrict__ out)
{
    extern __shared__ float sm[];
    float* As = sm;                  // [128][68] (d-major, padded)
    float* Wt = sm + 128 * 68;       // [128][132]

    const int b  = blockIdx.y;
    const int n0 = blockIdx.x * 64;
    const int tid = threadIdx.x;

    // Load A tile: As[d*68 + m] = attn[b, n0+m, d]  (coalesced global in d)
#pragma unroll
    for (int it = 0; it < 32; ++it) {
        int i = tid + it * 256;
        int m = i >> 7, d = i & 127;
        As[d * 68 + m] = g_attn[((size_t)b * N_SEQ + n0 + m) * D_MODEL + d];
    }
    // Load W transposed
#pragma unroll
    for (int it = 0; it < 64; ++it) {
        int i = tid + it * 256;
        int j = i >> 7, d = i & 127;
        Wt[d * 132 + j] = Wfc[i];
    }
    __syncthreads();

    const int tx = tid & 15;
    const int ty = tid >> 4;

    float c[4][8];
#pragma unroll
    for (int mm = 0; mm < 4; ++mm)
#pragma unroll
        for (int jj = 0; jj < 8; ++jj) c[mm][jj] = 0.f;

#pragma unroll 4
    for (int d = 0; d < 128; ++d) {
        float4 xv = *(const float4*)&As[d * 68 + tx * 4];
        float4 wa = *(const float4*)&Wt[d * 132 + ty * 8];
        float4 wb = *(const float4*)&Wt[d * 132 + ty * 8 + 4];
        float xs[4] = {xv.x, xv.y, xv.z, xv.w};
        float ws[8] = {wa.x, wa.y, wa.z, wa.w, wb.x, wb.y, wb.z, wb.w};
#pragma unroll
        for (int mm = 0; mm < 4; ++mm)
#pragma unroll
            for (int jj = 0; jj < 8; ++jj)
                c[mm][jj] = fmaf(xs[mm], ws[jj], c[mm][jj]);
    }

    // Write transposed: out[(b*128 + j)*2048 + n0 + m], vectorized over m
#pragma unroll
    for (int jj = 0; jj < 8; ++jj) {
        const int j = ty * 8 + jj;
        const float bias = bfc[j];
        float4 o = {c[0][jj] + bias, c[1][jj] + bias, c[2][jj] + bias, c[3][jj] + bias};
        *(float4*)&out[((size_t)b * D_MODEL + j) * N_SEQ + n0 + tx * 4] = o;
    }
}

// ---------------------------------------------------------------------------
extern "C" void kernel_launch(void* const* d_in, const int* in_sizes, int n_in,
                              void* d_out, int out_size)
{
    const float* x    = (const float*)d_in[0];
    const float* mask = (const float*)d_in[1];
    const float* Wq   = (const float*)d_in[2];
    const float* bq   = (const float*)d_in[3];
    const float* Wk   = (const float*)d_in[4];
    const float* bk   = (const float*)d_in[5];
    const float* Wv   = (const float*)d_in[6];
    const float* bv   = (const float*)d_in[7];
    const float* Wfc  = (const float*)d_in[8];
    const float* bfc  = (const float*)d_in[9];
    float* out = (float*)d_out;

    const size_t smem1 = (8192 + 128 * 132) * sizeof(float);       // 100352 B
    const size_t smem3 = (128 * 68 + 128 * 132) * sizeof(float);   // 102400 B
    cudaFuncSetAttribute(qkv_proj_kernel, cudaFuncAttributeMaxDynamicSharedMemorySize, (int)smem1);
    cudaFuncSetAttribute(fc_proj_kernel,  cudaFuncAttributeMaxDynamicSharedMemorySize, (int)smem3);

    qkv_proj_kernel<<<dim3(N_SEQ / 64, BATCH), 256, smem1>>>(x, Wq, bq, Wk, bk, Wv, bv);
    flash_attn_kernel<<<dim3(N_SEQ / 128, N_HEAD, BATCH), 128>>>(mask);
    fc_proj_kernel<<<dim3(N_SEQ / 64, BATCH), 256, smem3>>>(Wfc, bfc, out);
}

// round 3
// speedup vs baseline: 1.1061x; 1.1061x over previous
#include <cuda_runtime.h>
#include <cstdint>

#define D_MODEL 128
#define N_SEQ   2048
#define BATCH   4
#define N_HEAD  8
#define D_K     16
#define NEG_INF -1e30f
#define LOG2E   1.4426950408889634f

typedef unsigned long long ull;

__device__ __forceinline__ ull pack2(float lo, float hi) {
    ull r; asm("mov.b64 %0, {%1,%2};" : "=l"(r) : "f"(lo), "f"(hi)); return r;
}
__device__ __forceinline__ float2 unpk2(ull a) {
    float2 r; asm("mov.b64 {%0,%1}, %2;" : "=f"(r.x), "=f"(r.y) : "l"(a)); return r;
}
__device__ __forceinline__ ull ffma2(ull a, ull b, ull c) {
    ull d; asm("fma.rn.f32x2 %0, %1, %2, %3;" : "=l"(d) : "l"(a), "l"(b), "l"(c)); return d;
}
__device__ __forceinline__ ull fmul2(ull a, ull b) {
    ull d; asm("mul.rn.f32x2 %0, %1, %2;" : "=l"(d) : "l"(a), "l"(b)); return d;
}
__device__ __forceinline__ float ex2f(float x) {
    float y; asm("ex2.approx.f32 %0, %1;" : "=f"(y) : "f"(x)); return y;
}

// Scratch (device globals — no allocations allowed)
__device__ float g_q[BATCH * N_SEQ * D_MODEL];
__device__ float g_k[BATCH * N_SEQ * D_MODEL];
__device__ float g_v[BATCH * N_SEQ * D_MODEL];
__device__ float g_attn[BATCH * N_SEQ * D_MODEL];

// ---------------------------------------------------------------------------
// Kernel 1: QKV projection. x:(B,D,N) -> q/k/v:(B,N,D)
// Grid (32 n-tiles, B, 3 weights). 256 threads. K chunked by 32, f32x2 math.
// ---------------------------------------------------------------------------
__global__ __launch_bounds__(256) void qkv_proj_kernel(
    const float* __restrict__ x,
    const float* __restrict__ Wq, const float* __restrict__ bq,
    const float* __restrict__ Wk, const float* __restrict__ bk,
    const float* __restrict__ Wv, const float* __restrict__ bv)
{
    __shared__ float Xs[32 * 64];     // [d][m]
    __shared__ float Wt[32 * 132];    // [d][j] padded

    const int b  = blockIdx.y;
    const int n0 = blockIdx.x * 64;
    const int w  = blockIdx.z;
    const int tid = threadIdx.x;

    const float* W    = (w == 0) ? Wq : (w == 1) ? Wk : Wv;
    const float* bias = (w == 0) ? bq : (w == 1) ? bk : bv;
    float* O          = (w == 0) ? g_q : (w == 1) ? g_k : g_v;

    const int tx = tid & 15;   // m = tx*4 .. +3
    const int ty = tid >> 4;   // j = ty*8 .. +7

    ull c2[4][4];
#pragma unroll
    for (int mm = 0; mm < 4; ++mm)
#pragma unroll
        for (int jp = 0; jp < 4; ++jp) c2[mm][jp] = 0ULL;

#pragma unroll 1
    for (int kc = 0; kc < 4; ++kc) {
        __syncthreads();
        // Xs[dd][m] = x[b, kc*32+dd, n0+m] (coalesced in m, conflict-free store)
#pragma unroll
        for (int it = 0; it < 8; ++it) {
            int i = tid + it * 256;
            int dd = i >> 6, m = i & 63;
            Xs[i] = x[((size_t)b * D_MODEL + kc * 32 + dd) * N_SEQ + n0 + m];
        }
        // Wt[dd][j] = W[j, kc*32+dd] (coalesced global reads; 4-way smem conflict ok)
#pragma unroll
        for (int it = 0; it < 16; ++it) {
            int i = tid + it * 256;
            int j = i >> 5, dd = i & 31;
            Wt[dd * 132 + j] = W[j * D_MODEL + kc * 32 + dd];
        }
        __syncthreads();

#pragma unroll 8
        for (int d = 0; d < 32; ++d) {
            float4 xv = *(const float4*)&Xs[d * 64 + tx * 4];
            ulonglong2 wA = *(const ulonglong2*)&Wt[d * 132 + ty * 8];
            ulonglong2 wB = *(const ulonglong2*)&Wt[d * 132 + ty * 8 + 4];
            ull x2[4] = {pack2(xv.x, xv.x), pack2(xv.y, xv.y),
                         pack2(xv.z, xv.z), pack2(xv.w, xv.w)};
#pragma unroll
            for (int mm = 0; mm < 4; ++mm) {
                c2[mm][0] = ffma2(x2[mm], wA.x, c2[mm][0]);
                c2[mm][1] = ffma2(x2[mm], wA.y, c2[mm][1]);
                c2[mm][2] = ffma2(x2[mm], wB.x, c2[mm][2]);
                c2[mm][3] = ffma2(x2[mm], wB.y, c2[mm][3]);
            }
        }
    }

    float bi[8];
#pragma unroll
    for (int jj = 0; jj < 8; ++jj) bi[jj] = bias[ty * 8 + jj];

#pragma unroll
    for (int mm = 0; mm < 4; ++mm) {
        float2 p0 = unpk2(c2[mm][0]), p1 = unpk2(c2[mm][1]);
        float2 p2 = unpk2(c2[mm][2]), p3 = unpk2(c2[mm][3]);
        size_t base = ((size_t)b * N_SEQ + n0 + tx * 4 + mm) * D_MODEL + ty * 8;
        float4 o0 = {p0.x + bi[0], p0.y + bi[1], p1.x + bi[2], p1.y + bi[3]};
        float4 o1 = {p2.x + bi[4], p2.y + bi[5], p3.x + bi[6], p3.y + bi[7]};
        *(float4*)&O[base]     = o0;
        *(float4*)&O[base + 4] = o1;
    }
}

// ---------------------------------------------------------------------------
// Kernel 2: flash attention (f32x2 packed, log2-domain softmax).
// Grid (16 q-tiles, 8 heads, 4 batch), 128 threads; thread owns one q row.
// ---------------------------------------------------------------------------
__global__ __launch_bounds__(128) void flash_attn_kernel(
    const float* __restrict__ mask)
{
    __shared__ float  Ks[128 * 16];
    __shared__ float  Vs[128 * 16];
    __shared__ float2 Mb[128];     // (m, (1-m)*NEG_INF*log2e)

    const int qt = blockIdx.x, h = blockIdx.y, b = blockIdx.z;
    const int tid = threadIdx.x;
    const int n = qt * 128 + tid;

    const float scale = 0.08838834764831843f * LOG2E;  // 1/sqrt(128) * log2(e)

    const float* qp = g_q + ((size_t)b * N_SEQ + n) * D_MODEL + h * D_K;
    float4 q0 = *(const float4*)&qp[0];
    float4 q1 = *(const float4*)&qp[4];
    float4 q2 = *(const float4*)&qp[8];
    float4 q3 = *(const float4*)&qp[12];
    ull qv[8] = {
        pack2(q0.x * scale, q0.y * scale), pack2(q0.z * scale, q0.w * scale),
        pack2(q1.x * scale, q1.y * scale), pack2(q1.z * scale, q1.w * scale),
        pack2(q2.x * scale, q2.y * scale), pack2(q2.z * scale, q2.w * scale),
        pack2(q3.x * scale, q3.y * scale), pack2(q3.z * scale, q3.w * scale)};

    ull acc2[9];   // 8 pairs of output dims + (l,l)
#pragma unroll
    for (int i = 0; i < 9; ++i) acc2[i] = 0ULL;
    float m_run = -1e30f;
    const ull ONE2 = pack2(1.f, 1.f);

#pragma unroll 1
    for (int t = 0; t < 16; ++t) {
        const int kv0 = t * 128;
        {
            const float* kp = g_k + ((size_t)b * N_SEQ + kv0 + tid) * D_MODEL + h * D_K;
            const float* vp = g_v + ((size_t)b * N_SEQ + kv0 + tid) * D_MODEL + h * D_K;
            float4* kd = (float4*)&Ks[tid * 16];
            float4* vd = (float4*)&Vs[tid * 16];
            kd[0] = *(const float4*)&kp[0];  kd[1] = *(const float4*)&kp[4];
            kd[2] = *(const float4*)&kp[8];  kd[3] = *(const float4*)&kp[12];
            vd[0] = *(const float4*)&vp[0];  vd[1] = *(const float4*)&vp[4];
            vd[2] = *(const float4*)&vp[8];  vd[3] = *(const float4*)&vp[12];
            float mv = mask[(size_t)b * N_SEQ + kv0 + tid];
            Mb[tid] = make_float2(mv, (1.f - mv) * (NEG_INF * LOG2E));
        }
        __syncthreads();

#pragma unroll 1
        for (int c = 0; c < 4; ++c) {
            float s[32];
            float cmax = -1e30f;
#pragma unroll
            for (int jj = 0; jj < 32; ++jj) {
                const int j = c * 32 + jj;
                const ulonglong2* kr = (const ulonglong2*)&Ks[j * 16];
                ulonglong2 kA = kr[0], kB = kr[1];
                ull d2 = fmul2(qv[0], kA.x);
                d2 = ffma2(qv[1], kA.y, d2);
                d2 = ffma2(qv[2], kB.x, d2);
                d2 = ffma2(qv[3], kB.y, d2);
                ulonglong2 kC = kr[2], kD = kr[3];
                d2 = ffma2(qv[4], kC.x, d2);
                d2 = ffma2(qv[5], kC.y, d2);
                d2 = ffma2(qv[6], kD.x, d2);
                d2 = ffma2(qv[7], kD.y, d2);
                float2 dd = unpk2(d2);
                float dot = dd.x + dd.y;
                float2 mb = Mb[j];
                float sv = fmaf(dot, mb.x, mb.y);
                s[jj] = sv;
                cmax = fmaxf(cmax, sv);
            }
            const float m_new = fmaxf(m_run, cmax);
            const float corr = ex2f(m_run - m_new);
            const ull corr2 = pack2(corr, corr);
#pragma unroll
            for (int i = 0; i < 9; ++i) acc2[i] = fmul2(acc2[i], corr2);
#pragma unroll
            for (int jj = 0; jj < 32; ++jj) {
                const int j = c * 32 + jj;
                const float p = ex2f(s[jj] - m_new);
                const ull p2 = pack2(p, p);
                const ulonglong2* vr = (const ulonglong2*)&Vs[j * 16];
                ulonglong2 vA = vr[0], vB = vr[1];
                acc2[0] = ffma2(p2, vA.x, acc2[0]);
                acc2[1] = ffma2(p2, vA.y, acc2[1]);
                acc2[2] = ffma2(p2, vB.x, acc2[2]);
                acc2[3] = ffma2(p2, vB.y, acc2[3]);
                ulonglong2 vC = vr[2], vD = vr[3];
                acc2[4] = ffma2(p2, vC.x, acc2[4]);
                acc2[5] = ffma2(p2, vC.y, acc2[5]);
                acc2[6] = ffma2(p2, vD.x, acc2[6]);
                acc2[7] = ffma2(p2, vD.y, acc2[7]);
                acc2[8] = ffma2(p2, ONE2, acc2[8]);
            }
            m_run = m_new;
        }
        __syncthreads();
    }

    const float l = unpk2(acc2[8]).x;
    const float inv = 1.f / l;
    const ull inv2 = pack2(inv, inv);
    float* op = g_attn + ((size_t)b * N_SEQ + n) * D_MODEL + h * D_K;
#pragma unroll
    for (int i = 0; i < 4; ++i) {
        float2 a = unpk2(fmul2(acc2[2 * i], inv2));
        float2 bq2 = unpk2(fmul2(acc2[2 * i + 1], inv2));
        float4 o = {a.x, a.y, bq2.x, bq2.y};
        *(float4*)&op[i * 4] = o;
    }
}

// ---------------------------------------------------------------------------
// Kernel 3: FC projection + transpose. attn:(B,N,D) -> out:(B,D,N)
// ---------------------------------------------------------------------------
__global__ __launch_bounds__(256) void fc_proj_kernel(
    const float* __restrict__ Wfc, const float* __restrict__ bfc,
    float* __restrict__ out)
{
    __shared__ float As[32 * 68];     // [d][m] padded
    __shared__ float Wt[32 * 132];    // [d][j] padded

    const int b  = blockIdx.y;
    const int n0 = blockIdx.x * 64;
    const int tid = threadIdx.x;

    const int tx = tid & 15;
    const int ty = tid >> 4;

    ull c2[4][4];
#pragma unroll
    for (int mm = 0; mm < 4; ++mm)
#pragma unroll
        for (int jp = 0; jp < 4; ++jp) c2[mm][jp] = 0ULL;

#pragma unroll 1
    for (int kc = 0; kc < 4; ++kc) {
        __syncthreads();
        // As[dd][m] = attn[b, n0+m, kc*32+dd] (coalesced in dd)
#pragma unroll
        for (int it = 0; it < 8; ++it) {
            int i = tid + it * 256;
            int m = i >> 5, dd = i & 31;
            As[dd * 68 + m] = g_attn[((size_t)b * N_SEQ + n0 + m) * D_MODEL + kc * 32 + dd];
        }
#pragma unroll
        for (int it = 0; it < 16; ++it) {
            int i = tid + it * 256;
            int j = i >> 5, dd = i & 31;
            Wt[dd * 132 + j] = Wfc[j * D_MODEL + kc * 32 + dd];
        }
        __syncthreads();

#pragma unroll 8
        for (int d = 0; d < 32; ++d) {
            float4 xv = *(const float4*)&As[d * 68 + tx * 4];
            ulonglong2 wA = *(const ulonglong2*)&Wt[d * 132 + ty * 8];
            ulonglong2 wB = *(const ulonglong2*)&Wt[d * 132 + ty * 8 + 4];
            ull x2[4] = {pack2(xv.x, xv.x), pack2(xv.y, xv.y),
                         pack2(xv.z, xv.z), pack2(xv.w, xv.w)};
#pragma unroll
            for (int mm = 0; mm < 4; ++mm) {
                c2[mm][0] = ffma2(x2[mm], wA.x, c2[mm][0]);
                c2[mm][1] = ffma2(x2[mm], wA.y, c2[mm][1]);
                c2[mm][2] = ffma2(x2[mm], wB.x, c2[mm][2]);
                c2[mm][3] = ffma2(x2[mm], wB.y, c2[mm][3]);
            }
        }
    }

    // Unpack: cval[mm][jj]
    float cv[4][8];
#pragma unroll
    for (int mm = 0; mm < 4; ++mm)
#pragma unroll
        for (int jp = 0; jp < 4; ++jp) {
            float2 p = unpk2(c2[mm][jp]);
            cv[mm][2 * jp] = p.x; cv[mm][2 * jp + 1] = p.y;
        }

#pragma unroll
    for (int jj = 0; jj < 8; ++jj) {
        const int j = ty * 8 + jj;
        const float bias = bfc[j];
        float4 o = {cv[0][jj] + bias, cv[1][jj] + bias,
                    cv[2][jj] + bias, cv[3][jj] + bias};
        *(float4*)&out[((size_t)b * D_MODEL + j) * N_SEQ + n0 + tx * 4] = o;
    }
}

// ---------------------------------------------------------------------------
extern "C" void kernel_launch(void* const* d_in, const int* in_sizes, int n_in,
                              void* d_out, int out_size)
{
    const float* x    = (const float*)d_in[0];
    const float* mask = (const float*)d_in[1];
    const float* Wq   = (const float*)d_in[2];
    const float* bq   = (const float*)d_in[3];
    const float* Wk   = (const float*)d_in[4];
    const float* bk   = (const float*)d_in[5];
    const float* Wv   = (const float*)d_in[6];
    const float* bv   = (const float*)d_in[7];
    const float* Wfc  = (const float*)d_in[8];
    const float* bfc  = (const float*)d_in[9];
    float* out = (float*)d_out;

    qkv_proj_kernel<<<dim3(N_SEQ / 64, BATCH, 3), 256>>>(x, Wq, bq, Wk, bk, Wv, bv);
    flash_attn_kernel<<<dim3(N_SEQ / 128, N_HEAD, BATCH), 128>>>(mask);
    fc_proj_kernel<<<dim3(N_SEQ / 64, BATCH), 256>>>(Wfc, bfc, out);
}

// round 5
// speedup vs baseline: 2.1460x; 1.9402x over previous
#include <cuda_runtime.h>
#include <cuda_bf16.h>
#include <cstdint>

#define D_MODEL 128
#define N_SEQ   2048
#define BATCH   4
#define N_HEAD  8
#define D_K     16
#define NEG_INF -1e30f
#define LOG2E   1.4426950408889634f

typedef unsigned long long ull;

// ===================== f32x2 helpers (projection kernels) ====================
__device__ __forceinline__ ull pack2(float lo, float hi) {
    ull r; asm("mov.b64 %0, {%1,%2};" : "=l"(r) : "f"(lo), "f"(hi)); return r;
}
__device__ __forceinline__ float2 unpk2(ull a) {
    float2 r; asm("mov.b64 {%0,%1}, %2;" : "=f"(r.x), "=f"(r.y) : "l"(a)); return r;
}
__device__ __forceinline__ ull ffma2(ull a, ull b, ull c) {
    ull d; asm("fma.rn.f32x2 %0, %1, %2, %3;" : "=l"(d) : "l"(a), "l"(b), "l"(c)); return d;
}
__device__ __forceinline__ float ex2f(float x) {
    float y; asm("ex2.approx.f32 %0, %1;" : "=f"(y) : "f"(x)); return y;
}

// split a float pair into bf16x2 hi + bf16x2 lo (lo = residual)
__device__ __forceinline__ void split_pair(float a, float b, uint32_t& hi, uint32_t& lo) {
    asm("cvt.rn.bf16x2.f32 %0, %1, %2;" : "=r"(hi) : "f"(b), "f"(a));
    float ha = __uint_as_float(hi << 16);
    float hb = __uint_as_float(hi & 0xffff0000u);
    float ra = a - ha, rb = b - hb;
    asm("cvt.rn.bf16x2.f32 %0, %1, %2;" : "=r"(lo) : "f"(rb), "f"(ra));
}

// mma.sync m16n8k16 bf16 (row.col), fp32 accum — baseline PTX, works on sm_103
__device__ __forceinline__ void mma16816(float* c, const uint32_t* a, const uint32_t* b) {
    asm volatile("mma.sync.aligned.m16n8k16.row.col.f32.bf16.bf16.f32 "
        "{%0,%1,%2,%3}, {%4,%5,%6,%7}, {%8,%9}, {%0,%1,%2,%3};"
        : "+f"(c[0]), "+f"(c[1]), "+f"(c[2]), "+f"(c[3])
        : "r"(a[0]), "r"(a[1]), "r"(a[2]), "r"(a[3]), "r"(b[0]), "r"(b[1]));
}

// ===================== scratch ==============================================
__device__ float g_q[BATCH * N_SEQ * D_MODEL];
__device__ float g_k[BATCH * N_SEQ * D_MODEL];
__device__ float g_v[BATCH * N_SEQ * D_MODEL];
__device__ float g_attn[BATCH * N_SEQ * D_MODEL];

// ===================== Kernel 1: QKV projection =============================
__global__ __launch_bounds__(256) void qkv_proj_kernel(
    const float* __restrict__ x,
    const float* __restrict__ Wq, const float* __restrict__ bq,
    const float* __restrict__ Wk, const float* __restrict__ bk,
    const float* __restrict__ Wv, const float* __restrict__ bv)
{
    __shared__ float Xs[32 * 64];
    __shared__ float Wt[32 * 132];

    const int b  = blockIdx.y;
    const int n0 = blockIdx.x * 64;
    const int w  = blockIdx.z;
    const int tid = threadIdx.x;

    const float* W    = (w == 0) ? Wq : (w == 1) ? Wk : Wv;
    const float* bias = (w == 0) ? bq : (w == 1) ? bk : bv;
    float* O          = (w == 0) ? g_q : (w == 1) ? g_k : g_v;

    const int tx = tid & 15, ty = tid >> 4;

    ull c2[4][4];
#pragma unroll
    for (int mm = 0; mm < 4; ++mm)
#pragma unroll
        for (int jp = 0; jp < 4; ++jp) c2[mm][jp] = 0ULL;

#pragma unroll 1
    for (int kc = 0; kc < 4; ++kc) {
        __syncthreads();
#pragma unroll
        for (int it = 0; it < 8; ++it) {
            int i = tid + it * 256;
            int dd = i >> 6, m = i & 63;
            Xs[i] = x[((size_t)b * D_MODEL + kc * 32 + dd) * N_SEQ + n0 + m];
        }
#pragma unroll
        for (int it = 0; it < 16; ++it) {
            int i = tid + it * 256;
            int j = i >> 5, dd = i & 31;
            Wt[dd * 132 + j] = W[j * D_MODEL + kc * 32 + dd];
        }
        __syncthreads();

#pragma unroll 8
        for (int d = 0; d < 32; ++d) {
            float4 xv = *(const float4*)&Xs[d * 64 + tx * 4];
            ulonglong2 wA = *(const ulonglong2*)&Wt[d * 132 + ty * 8];
            ulonglong2 wB = *(const ulonglong2*)&Wt[d * 132 + ty * 8 + 4];
            ull x2[4] = {pack2(xv.x, xv.x), pack2(xv.y, xv.y),
                         pack2(xv.z, xv.z), pack2(xv.w, xv.w)};
#pragma unroll
            for (int mm = 0; mm < 4; ++mm) {
                c2[mm][0] = ffma2(x2[mm], wA.x, c2[mm][0]);
                c2[mm][1] = ffma2(x2[mm], wA.y, c2[mm][1]);
                c2[mm][2] = ffma2(x2[mm], wB.x, c2[mm][2]);
                c2[mm][3] = ffma2(x2[mm], wB.y, c2[mm][3]);
            }
        }
    }

    float bi[8];
#pragma unroll
    for (int jj = 0; jj < 8; ++jj) bi[jj] = bias[ty * 8 + jj];

#pragma unroll
    for (int mm = 0; mm < 4; ++mm) {
        float2 p0 = unpk2(c2[mm][0]), p1 = unpk2(c2[mm][1]);
        float2 p2 = unpk2(c2[mm][2]), p3 = unpk2(c2[mm][3]);
        size_t base = ((size_t)b * N_SEQ + n0 + tx * 4 + mm) * D_MODEL + ty * 8;
        float4 o0 = {p0.x + bi[0], p0.y + bi[1], p1.x + bi[2], p1.y + bi[3]};
        float4 o1 = {p2.x + bi[4], p2.y + bi[5], p3.x + bi[6], p3.y + bi[7]};
        *(float4*)&O[base]     = o0;
        *(float4*)&O[base + 4] = o1;
    }
}

// ===================== Kernel 2: mma.sync flash attention ===================
// Grid (16 q-tiles, 8 heads, 4 batch). 128 threads = 4 warps; warp w owns q
// rows 32w..32w+31 (two m16 tiles). All GEMMs via mma.sync bf16 with hi/lo
// precision splits; P stays in registers (C-fragment of S == A-fragment of P).

__global__ __launch_bounds__(128) void flash_attn_mma_kernel(
    const float* __restrict__ mask)
{
    // K rows padded to 20 bf16 (40B); Vt rows padded to 132 bf16 (264B)
    __shared__ __align__(16) unsigned short Qhi_s[128][20], Qlo_s[128][20];
    __shared__ __align__(16) unsigned short Khi_s[128][20], Klo_s[128][20];
    __shared__ __align__(16) unsigned short Vthi_s[16][132], Vtlo_s[16][132];
    __shared__ float sb[128];

    const int qt = blockIdx.x, h = blockIdx.y, b = blockIdx.z;
    const int tid  = threadIdx.x;
    const int warp = tid >> 5;
    const int lane = tid & 31;
    const int g  = lane >> 2;       // row group 0..7
    const int m4 = lane & 3;        // col/k quad 0..3

    uint32_t* Qhi32 = (uint32_t*)Qhi_s;
    uint32_t* Qlo32 = (uint32_t*)Qlo_s;
    const uint32_t* Khi32 = (const uint32_t*)Khi_s;
    const uint32_t* Klo32 = (const uint32_t*)Klo_s;
    const uint32_t* Vthi32 = (const uint32_t*)Vthi_s;
    const uint32_t* Vtlo32 = (const uint32_t*)Vtlo_s;

    // --- load + split Q (scale*log2e folded) into smem ---
    const float qscale = 0.08838834764831843f * LOG2E;
    {
        const float* qp = g_q + ((size_t)b * N_SEQ + qt * 128 + tid) * D_MODEL + h * D_K;
        float q[16];
        *(float4*)&q[0]  = *(const float4*)&qp[0];
        *(float4*)&q[4]  = *(const float4*)&qp[4];
        *(float4*)&q[8]  = *(const float4*)&qp[8];
        *(float4*)&q[12] = *(const float4*)&qp[12];
#pragma unroll
        for (int i = 0; i < 8; ++i) {
            uint32_t hi, lo;
            split_pair(q[2 * i] * qscale, q[2 * i + 1] * qscale, hi, lo);
            Qhi32[tid * 10 + i] = hi;
            Qlo32[tid * 10 + i] = lo;
        }
    }
    __syncthreads();

    // --- hoist Q fragments (loop-invariant) ---
    uint32_t aQh[2][4], aQl[2][4];
#pragma unroll
    for (int mt = 0; mt < 2; ++mt) {
        const int r0 = warp * 32 + mt * 16 + g;
        aQh[mt][0] = Qhi32[r0 * 10 + m4];
        aQh[mt][1] = Qhi32[(r0 + 8) * 10 + m4];
        aQh[mt][2] = Qhi32[r0 * 10 + 4 + m4];
        aQh[mt][3] = Qhi32[(r0 + 8) * 10 + 4 + m4];
        aQl[mt][0] = Qlo32[r0 * 10 + m4];
        aQl[mt][1] = Qlo32[(r0 + 8) * 10 + m4];
        aQl[mt][2] = Qlo32[r0 * 10 + 4 + m4];
        aQl[mt][3] = Qlo32[(r0 + 8) * 10 + 4 + m4];
    }

    // per-lane row state: [mt][row-half (g / g+8)]
    float o[2][2][4];
#pragma unroll
    for (int mt = 0; mt < 2; ++mt)
#pragma unroll
        for (int n = 0; n < 2; ++n)
#pragma unroll
            for (int i = 0; i < 4; ++i) o[mt][n][i] = 0.f;
    float m_run[2][2] = {{-1e30f, -1e30f}, {-1e30f, -1e30f}};
    float lsum[2][2]  = {{0.f, 0.f}, {0.f, 0.f}};

#pragma unroll 1
    for (int t = 0; t < 16; ++t) {
        // --- load + split K row & V row (V transposed) ---
        {
            const size_t rb = ((size_t)b * N_SEQ + t * 128 + tid) * D_MODEL + h * D_K;
            const float* kp = g_k + rb;
            float k[16];
            *(float4*)&k[0]  = *(const float4*)&kp[0];
            *(float4*)&k[4]  = *(const float4*)&kp[4];
            *(float4*)&k[8]  = *(const float4*)&kp[8];
            *(float4*)&k[12] = *(const float4*)&kp[12];
#pragma unroll
            for (int i = 0; i < 8; ++i) {
                uint32_t hi, lo;
                split_pair(k[2 * i], k[2 * i + 1], hi, lo);
                ((uint32_t*)Khi_s)[tid * 10 + i] = hi;
                ((uint32_t*)Klo_s)[tid * 10 + i] = lo;
            }
            const float* vp = g_v + rb;
            float v[16];
            *(float4*)&v[0]  = *(const float4*)&vp[0];
            *(float4*)&v[4]  = *(const float4*)&vp[4];
            *(float4*)&v[8]  = *(const float4*)&vp[8];
            *(float4*)&v[12] = *(const float4*)&vp[12];
#pragma unroll
            for (int i = 0; i < 8; ++i) {
                uint32_t hi, lo;
                split_pair(v[2 * i], v[2 * i + 1], hi, lo);
                Vthi_s[2 * i][tid]     = (unsigned short)(hi & 0xffff);
                Vthi_s[2 * i + 1][tid] = (unsigned short)(hi >> 16);
                Vtlo_s[2 * i][tid]     = (unsigned short)(lo & 0xffff);
                Vtlo_s[2 * i + 1][tid] = (unsigned short)(lo >> 16);
            }
            float mv = mask[(size_t)b * N_SEQ + t * 128 + tid];
            sb[tid] = (1.f - mv) * (NEG_INF * LOG2E);
        }
        const int any_mask = __syncthreads_or(sb[tid] != 0.f);

#pragma unroll 1
        for (int mt = 0; mt < 2; ++mt) {
            // ---- S = Q·K^T (3-way split) ----
            float s[16][4];
#pragma unroll
            for (int j = 0; j < 16; ++j) {
                s[j][0] = s[j][1] = s[j][2] = s[j][3] = 0.f;
                const int kr = (8 * j + g) * 10;
                uint32_t bh[2] = {Khi32[kr + m4], Khi32[kr + 4 + m4]};
                uint32_t bl[2] = {Klo32[kr + m4], Klo32[kr + 4 + m4]};
                mma16816(s[j], aQh[mt], bh);
                mma16816(s[j], aQh[mt], bl);
                mma16816(s[j], aQl[mt], bh);
            }
            // ---- mask bias ----
            if (any_mask) {
#pragma unroll
                for (int j = 0; j < 16; ++j) {
                    float2 sv = *(const float2*)&sb[8 * j + 2 * m4];
                    s[j][0] += sv.x; s[j][1] += sv.y;
                    s[j][2] += sv.x; s[j][3] += sv.y;
                }
            }
            // ---- row max (2 rows per lane) ----
            float mx0 = s[0][0], mx1 = s[0][2];
#pragma unroll
            for (int j = 0; j < 16; ++j) {
                mx0 = fmaxf(mx0, fmaxf(s[j][0], s[j][1]));
                mx1 = fmaxf(mx1, fmaxf(s[j][2], s[j][3]));
            }
            mx0 = fmaxf(mx0, __shfl_xor_sync(0xffffffffu, mx0, 1));
            mx0 = fmaxf(mx0, __shfl_xor_sync(0xffffffffu, mx0, 2));
            mx1 = fmaxf(mx1, __shfl_xor_sync(0xffffffffu, mx1, 1));
            mx1 = fmaxf(mx1, __shfl_xor_sync(0xffffffffu, mx1, 2));

            const float mn0 = fmaxf(m_run[mt][0], mx0);
            const float mn1 = fmaxf(m_run[mt][1], mx1);
            const float c0 = ex2f(m_run[mt][0] - mn0);
            const float c1 = ex2f(m_run[mt][1] - mn1);
            m_run[mt][0] = mn0; m_run[mt][1] = mn1;
            lsum[mt][0] *= c0; lsum[mt][1] *= c1;
#pragma unroll
            for (int n = 0; n < 2; ++n) {
                o[mt][n][0] *= c0; o[mt][n][1] *= c0;
                o[mt][n][2] *= c1; o[mt][n][3] *= c1;
            }
            // ---- exp + accumulate l (in place) ----
            float la0 = 0.f, la1 = 0.f;
#pragma unroll
            for (int j = 0; j < 16; ++j) {
                s[j][0] = ex2f(s[j][0] - mn0);
                s[j][1] = ex2f(s[j][1] - mn0);
                s[j][2] = ex2f(s[j][2] - mn1);
                s[j][3] = ex2f(s[j][3] - mn1);
                la0 += s[j][0] + s[j][1];
                la1 += s[j][2] + s[j][3];
            }
            lsum[mt][0] += la0; lsum[mt][1] += la1;

            // ---- PV: O += P·V (3-way split) ----
#pragma unroll
            for (int c = 0; c < 8; ++c) {
                uint32_t ah[4], al[4];
                split_pair(s[2 * c][0],     s[2 * c][1],     ah[0], al[0]);
                split_pair(s[2 * c][2],     s[2 * c][3],     ah[1], al[1]);
                split_pair(s[2 * c + 1][0], s[2 * c + 1][1], ah[2], al[2]);
                split_pair(s[2 * c + 1][2], s[2 * c + 1][3], ah[3], al[3]);
#pragma unroll
                for (int n = 0; n < 2; ++n) {
                    const int vr = (8 * n + g) * 66 + 8 * c;
                    uint32_t bh[2] = {Vthi32[vr + m4], Vthi32[vr + 4 + m4]};
                    uint32_t bl[2] = {Vtlo32[vr + m4], Vtlo32[vr + 4 + m4]};
                    mma16816(o[mt][n], ah, bh);
                    mma16816(o[mt][n], al, bh);
                    mma16816(o[mt][n], ah, bl);
                }
            }
        }
        __syncthreads();
    }

    // ---- epilogue: reduce l across the 4 lanes of each row, normalize ----
#pragma unroll
    for (int mt = 0; mt < 2; ++mt) {
        float l0 = lsum[mt][0], l1 = lsum[mt][1];
        l0 += __shfl_xor_sync(0xffffffffu, l0, 1);
        l0 += __shfl_xor_sync(0xffffffffu, l0, 2);
        l1 += __shfl_xor_sync(0xffffffffu, l1, 1);
        l1 += __shfl_xor_sync(0xffffffffu, l1, 2);
        const float i0 = 1.f / l0, i1 = 1.f / l1;
        const int r0 = qt * 128 + warp * 32 + mt * 16 + g;
#pragma unroll
        for (int n = 0; n < 2; ++n) {
            const int dim = h * D_K + 8 * n + 2 * m4;
            float2 lo = {o[mt][n][0] * i0, o[mt][n][1] * i0};
            float2 hi = {o[mt][n][2] * i1, o[mt][n][3] * i1};
            *(float2*)&g_attn[((size_t)b * N_SEQ + r0) * D_MODEL + dim]     = lo;
            *(float2*)&g_attn[((size_t)b * N_SEQ + r0 + 8) * D_MODEL + dim] = hi;
        }
    }
}

// ===================== Kernel 3: FC projection + transpose ==================
__global__ __launch_bounds__(256) void fc_proj_kernel(
    const float* __restrict__ Wfc, const float* __restrict__ bfc,
    float* __restrict__ out)
{
    __shared__ float As[32 * 68];
    __shared__ float Wt[32 * 132];

    const int b  = blockIdx.y;
    const int n0 = blockIdx.x * 64;
    const int tid = threadIdx.x;
    const int tx = tid & 15, ty = tid >> 4;

    ull c2[4][4];
#pragma unroll
    for (int mm = 0; mm < 4; ++mm)
#pragma unroll
        for (int jp = 0; jp < 4; ++jp) c2[mm][jp] = 0ULL;

#pragma unroll 1
    for (int kc = 0; kc < 4; ++kc) {
        __syncthreads();
#pragma unroll
        for (int it = 0; it < 8; ++it) {
            int i = tid + it * 256;
            int m = i >> 5, dd = i & 31;
            As[dd * 68 + m] = g_attn[((size_t)b * N_SEQ + n0 + m) * D_MODEL + kc * 32 + dd];
        }
#pragma unroll
        for (int it = 0; it < 16; ++it) {
            int i = tid + it * 256;
            int j = i >> 5, dd = i & 31;
            Wt[dd * 132 + j] = Wfc[j * D_MODEL + kc * 32 + dd];
        }
        __syncthreads();

#pragma unroll 8
        for (int d = 0; d < 32; ++d) {
            float4 xv = *(const float4*)&As[d * 68 + tx * 4];
            ulonglong2 wA = *(const ulonglong2*)&Wt[d * 132 + ty * 8];
            ulonglong2 wB = *(const ulonglong2*)&Wt[d * 132 + ty * 8 + 4];
            ull x2[4] = {pack2(xv.x, xv.x), pack2(xv.y, xv.y),
                         pack2(xv.z, xv.z), pack2(xv.w, xv.w)};
#pragma unroll
            for (int mm = 0; mm < 4; ++mm) {
                c2[mm][0] = ffma2(x2[mm], wA.x, c2[mm][0]);
                c2[mm][1] = ffma2(x2[mm], wA.y, c2[mm][1]);
                c2[mm][2] = ffma2(x2[mm], wB.x, c2[mm][2]);
                c2[mm][3] = ffma2(x2[mm], wB.y, c2[mm][3]);
            }
        }
    }

    float cv[4][8];
#pragma unroll
    for (int mm = 0; mm < 4; ++mm)
#pragma unroll
        for (int jp = 0; jp < 4; ++jp) {
            float2 p = unpk2(c2[mm][jp]);
            cv[mm][2 * jp] = p.x; cv[mm][2 * jp + 1] = p.y;
        }

#pragma unroll
    for (int jj = 0; jj < 8; ++jj) {
        const int j = ty * 8 + jj;
        const float bias = bfc[j];
        float4 o = {cv[0][jj] + bias, cv[1][jj] + bias,
                    cv[2][jj] + bias, cv[3][jj] + bias};
        *(float4*)&out[((size_t)b * D_MODEL + j) * N_SEQ + n0 + tx * 4] = o;
    }
}

// ===========================================================================
extern "C" void kernel_launch(void* const* d_in, const int* in_sizes, int n_in,
                              void* d_out, int out_size)
{
    const float* x    = (const float*)d_in[0];
    const float* mask = (const float*)d_in[1];
    const float* Wq   = (const float*)d_in[2];
    const float* bq   = (const float*)d_in[3];
    const float* Wk   = (const float*)d_in[4];
    const float* bk   = (const float*)d_in[5];
    const float* Wv   = (const float*)d_in[6];
    const float* bv   = (const float*)d_in[7];
    const float* Wfc  = (const float*)d_in[8];
    const float* bfc  = (const float*)d_in[9];
    float* out = (float*)d_out;

    qkv_proj_kernel<<<dim3(N_SEQ / 64, BATCH, 3), 256>>>(x, Wq, bq, Wk, bk, Wv, bv);
    flash_attn_mma_kernel<<<dim3(N_SEQ / 128, N_HEAD, BATCH), 128>>>(mask);
    fc_proj_kernel<<<dim3(N_SEQ / 64, BATCH), 256>>>(Wfc, bfc, out);
}

// round 7
// speedup vs baseline: 2.7492x; 1.2810x over previous
#include <cuda_runtime.h>
#include <cuda_bf16.h>
#include <cstdint>

#define D_MODEL 128
#define N_SEQ   2048
#define BATCH   4
#define N_HEAD  8
#define D_K     16
#define NEG_INF -1e30f
#define LOG2E   1.4426950408889634f

typedef unsigned long long ull;
typedef unsigned short u16;

// ===================== f32x2 helpers ========================================
__device__ __forceinline__ ull pack2(float lo, float hi) {
    ull r; asm("mov.b64 %0, {%1,%2};" : "=l"(r) : "f"(lo), "f"(hi)); return r;
}
__device__ __forceinline__ float2 unpk2(ull a) {
    float2 r; asm("mov.b64 {%0,%1}, %2;" : "=f"(r.x), "=f"(r.y) : "l"(a)); return r;
}
__device__ __forceinline__ ull ffma2(ull a, ull b, ull c) {
    ull d; asm("fma.rn.f32x2 %0, %1, %2, %3;" : "=l"(d) : "l"(a), "l"(b), "l"(c)); return d;
}
__device__ __forceinline__ float ex2f(float x) {
    float y; asm("ex2.approx.f32 %0, %1;" : "=f"(y) : "f"(x)); return y;
}

// split a float pair into bf16x2 hi + bf16x2 lo (lo = residual)
__device__ __forceinline__ void split_pair(float a, float b, uint32_t& hi, uint32_t& lo) {
    asm("cvt.rn.bf16x2.f32 %0, %1, %2;" : "=r"(hi) : "f"(b), "f"(a));
    float ha = __uint_as_float(hi << 16);
    float hb = __uint_as_float(hi & 0xffff0000u);
    float ra = a - ha, rb = b - hb;
    asm("cvt.rn.bf16x2.f32 %0, %1, %2;" : "=r"(lo) : "f"(rb), "f"(ra));
}

// mma.sync m16n8k16 bf16 (row.col), fp32 accum
__device__ __forceinline__ void mma16816(float* c, const uint32_t* a, const uint32_t* b) {
    asm volatile("mma.sync.aligned.m16n8k16.row.col.f32.bf16.bf16.f32 "
        "{%0,%1,%2,%3}, {%4,%5,%6,%7}, {%8,%9}, {%0,%1,%2,%3};"
        : "+f"(c[0]), "+f"(c[1]), "+f"(c[2]), "+f"(c[3])
        : "r"(a[0]), "r"(a[1]), "r"(a[2]), "r"(a[3]), "r"(b[0]), "r"(b[1]));
}

// ===================== scratch ==============================================
// pre-split bf16 tensors, head-blocked layouts
// Q/K: [bh][n][16]   V^T: [bh][16][N]
__device__ u16 g_qhi[32 * N_SEQ * 16], g_qlo[32 * N_SEQ * 16];
__device__ u16 g_khi[32 * N_SEQ * 16], g_klo[32 * N_SEQ * 16];
__device__ u16 g_vthi[32 * 16 * N_SEQ], g_vtlo[32 * 16 * N_SEQ];
__device__ float g_attn[BATCH * N_SEQ * D_MODEL];

// ===================== Kernel 1: QKV projection + bf16 split ================
// x:(B,D,N). Output: split bf16 arrays above (scale folded into Q).
__global__ __launch_bounds__(256) void qkv_proj_kernel(
    const float* __restrict__ x,
    const float* __restrict__ Wq, const float* __restrict__ bq,
    const float* __restrict__ Wk, const float* __restrict__ bk,
    const float* __restrict__ Wv, const float* __restrict__ bv)
{
    __shared__ float Xs[32 * 64];
    __shared__ float Wt[32 * 132];

    const int b  = blockIdx.y;
    const int n0 = blockIdx.x * 64;
    const int w  = blockIdx.z;
    const int tid = threadIdx.x;

    const float* W    = (w == 0) ? Wq : (w == 1) ? Wk : Wv;
    const float* bias = (w == 0) ? bq : (w == 1) ? bk : bv;

    const int tx = tid & 15, ty = tid >> 4;

    ull c2[4][4];
#pragma unroll
    for (int mm = 0; mm < 4; ++mm)
#pragma unroll
        for (int jp = 0; jp < 4; ++jp) c2[mm][jp] = 0ULL;

#pragma unroll 1
    for (int kc = 0; kc < 4; ++kc) {
        __syncthreads();
#pragma unroll
        for (int it = 0; it < 8; ++it) {
            int i = tid + it * 256;
            int dd = i >> 6, m = i & 63;
            Xs[i] = x[((size_t)b * D_MODEL + kc * 32 + dd) * N_SEQ + n0 + m];
        }
#pragma unroll
        for (int it = 0; it < 16; ++it) {
            int i = tid + it * 256;
            int j = i >> 5, dd = i & 31;
            Wt[dd * 132 + j] = W[j * D_MODEL + kc * 32 + dd];
        }
        __syncthreads();

#pragma unroll 8
        for (int d = 0; d < 32; ++d) {
            float4 xv = *(const float4*)&Xs[d * 64 + tx * 4];
            ulonglong2 wA = *(const ulonglong2*)&Wt[d * 132 + ty * 8];
            ulonglong2 wB = *(const ulonglong2*)&Wt[d * 132 + ty * 8 + 4];
            ull x2[4] = {pack2(xv.x, xv.x), pack2(xv.y, xv.y),
                         pack2(xv.z, xv.z), pack2(xv.w, xv.w)};
#pragma unroll
            for (int mm = 0; mm < 4; ++mm) {
                c2[mm][0] = ffma2(x2[mm], wA.x, c2[mm][0]);
                c2[mm][1] = ffma2(x2[mm], wA.y, c2[mm][1]);
                c2[mm][2] = ffma2(x2[mm], wB.x, c2[mm][2]);
                c2[mm][3] = ffma2(x2[mm], wB.y, c2[mm][3]);
            }
        }
    }

    float bi[8];
#pragma unroll
    for (int jj = 0; jj < 8; ++jj) bi[jj] = bias[ty * 8 + jj];

    // this thread's output: rows n0+tx*4+mm, dims j = ty*8 .. +7
    const int h    = ty >> 1;          // head
    const int dblk = (ty & 1) * 8;     // dim offset within head
    const int bh   = b * N_HEAD + h;
    const float qscale = 0.08838834764831843f * LOG2E;

    float cv[4][8];
#pragma unroll
    for (int mm = 0; mm < 4; ++mm)
#pragma unroll
        for (int jp = 0; jp < 4; ++jp) {
            float2 p = unpk2(c2[mm][jp]);
            cv[mm][2 * jp] = p.x + bi[2 * jp];
            cv[mm][2 * jp + 1] = p.y + bi[2 * jp + 1];
        }

    if (w == 2) {
        // V: write transposed hi/lo  [bh][d][n]
        uint32_t vh[4][4], vl[4][4];
#pragma unroll
        for (int mm = 0; mm < 4; ++mm)
#pragma unroll
            for (int jp = 0; jp < 4; ++jp)
                split_pair(cv[mm][2 * jp], cv[mm][2 * jp + 1], vh[mm][jp], vl[mm][jp]);
#pragma unroll
        for (int jj = 0; jj < 8; ++jj) {
            const int jp = jj >> 1, sh = (jj & 1) * 16;
            ushort4 oh = {(u16)(vh[0][jp] >> sh), (u16)(vh[1][jp] >> sh),
                          (u16)(vh[2][jp] >> sh), (u16)(vh[3][jp] >> sh)};
            ushort4 ol = {(u16)(vl[0][jp] >> sh), (u16)(vl[1][jp] >> sh),
                          (u16)(vl[2][jp] >> sh), (u16)(vl[3][jp] >> sh)};
            size_t base = ((size_t)bh * 16 + dblk + jj) * N_SEQ + n0 + tx * 4;
            *(ushort4*)&g_vthi[base] = oh;
            *(ushort4*)&g_vtlo[base] = ol;
        }
    } else {
        u16* Ohi = (w == 0) ? g_qhi : g_khi;
        u16* Olo = (w == 0) ? g_qlo : g_klo;
        const float sc = (w == 0) ? qscale : 1.f;
#pragma unroll
        for (int mm = 0; mm < 4; ++mm) {
            uint32_t hi[4], lo[4];
#pragma unroll
            for (int jp = 0; jp < 4; ++jp)
                split_pair(cv[mm][2 * jp] * sc, cv[mm][2 * jp + 1] * sc, hi[jp], lo[jp]);
            size_t base = ((size_t)bh * N_SEQ + n0 + tx * 4 + mm) * 16 + dblk;
            *(uint4*)&Ohi[base] = make_uint4(hi[0], hi[1], hi[2], hi[3]);
            *(uint4*)&Olo[base] = make_uint4(lo[0], lo[1], lo[2], lo[3]);
        }
    }
}

// ===================== Kernel 2: mma.sync flash attention ===================
// Grid (16 q-tiles, 8 heads, 4 batch). 256 threads = 8 warps; warp owns one
// m16 tile (16 q rows). K/V arrive pre-split bf16; threads 0-127 stage K,
// threads 128-255 stage V^T.
#define KSTRIDE 12   // dwords per K row (48B, 16B-aligned)
#define VSTRIDE 68   // dwords per Vt row (272B)

__global__ __launch_bounds__(256) void flash_attn_mma_kernel(
    const float* __restrict__ mask)
{
    __shared__ __align__(16) uint32_t Khi_s[128 * KSTRIDE], Klo_s[128 * KSTRIDE];
    __shared__ __align__(16) uint32_t Vthi_s[16 * VSTRIDE], Vtlo_s[16 * VSTRIDE];
    __shared__ float sb[128];

    const int qt = blockIdx.x, h = blockIdx.y, b = blockIdx.z;
    const int bh = b * N_HEAD + h;
    const int tid  = threadIdx.x;
    const int warp = tid >> 5;
    const int lane = tid & 31;
    const int g  = lane >> 2;
    const int m4 = lane & 3;

    // --- Q fragments straight from global (pre-scaled, pre-split) ---
    uint32_t aQh[4], aQl[4];
    {
        const uint32_t* qh = (const uint32_t*)g_qhi + (size_t)bh * N_SEQ * 8;
        const uint32_t* ql = (const uint32_t*)g_qlo + (size_t)bh * N_SEQ * 8;
        const int r0 = qt * 128 + warp * 16 + g, r1 = r0 + 8;
        aQh[0] = qh[r0 * 8 + m4];     aQh[1] = qh[r1 * 8 + m4];
        aQh[2] = qh[r0 * 8 + 4 + m4]; aQh[3] = qh[r1 * 8 + 4 + m4];
        aQl[0] = ql[r0 * 8 + m4];     aQl[1] = ql[r1 * 8 + m4];
        aQl[2] = ql[r0 * 8 + 4 + m4]; aQl[3] = ql[r1 * 8 + 4 + m4];
    }

    float o[2][4];
#pragma unroll
    for (int n = 0; n < 2; ++n)
#pragma unroll
        for (int i = 0; i < 4; ++i) o[n][i] = 0.f;
    float m_run0 = -1e30f, m_run1 = -1e30f;
    float lsum0 = 0.f, lsum1 = 0.f;

#pragma unroll 1
    for (int t = 0; t < 16; ++t) {
        // --- stage K (tid<128) / V (tid>=128) tiles, bf16 already split ---
        int pred = 0;
        if (tid < 128) {
            const size_t rb = ((size_t)bh * N_SEQ + t * 128 + tid) * 16;
            const uint4* kh = (const uint4*)&g_khi[rb];
            const uint4* kl = (const uint4*)&g_klo[rb];
            uint4 h0 = kh[0], h1 = kh[1], l0 = kl[0], l1 = kl[1];
            *(uint4*)&Khi_s[tid * KSTRIDE]     = h0;
            *(uint4*)&Khi_s[tid * KSTRIDE + 4] = h1;
            *(uint4*)&Klo_s[tid * KSTRIDE]     = l0;
            *(uint4*)&Klo_s[tid * KSTRIDE + 4] = l1;
            float mv = mask[(size_t)b * N_SEQ + t * 128 + tid];
            float bias = (1.f - mv) * (NEG_INF * LOG2E);
            sb[tid] = bias;
            pred = (bias != 0.f);
        } else {
            const int t2 = tid - 128;
            const int row = t2 >> 3, seg = t2 & 7;     // 16 rows x 8 segs of 32B
            const size_t sbase = ((size_t)bh * 16 + row) * N_SEQ + t * 128 + seg * 16;
            const uint4* vh = (const uint4*)&g_vthi[sbase];
            const uint4* vl = (const uint4*)&g_vtlo[sbase];
            uint4 h0 = vh[0], h1 = vh[1], l0 = vl[0], l1 = vl[1];
            *(uint4*)&Vthi_s[row * VSTRIDE + seg * 8]     = h0;
            *(uint4*)&Vthi_s[row * VSTRIDE + seg * 8 + 4] = h1;
            *(uint4*)&Vtlo_s[row * VSTRIDE + seg * 8]     = l0;
            *(uint4*)&Vtlo_s[row * VSTRIDE + seg * 8 + 4] = l1;
        }
        const int any_mask = __syncthreads_or(pred);

        // ---- S = Q·K^T (3-way split) ----
        float s[16][4];
#pragma unroll
        for (int j = 0; j < 16; ++j) {
            s[j][0] = s[j][1] = s[j][2] = s[j][3] = 0.f;
            const int kr = (8 * j + g) * KSTRIDE;
            uint32_t bhh[2] = {Khi_s[kr + m4], Khi_s[kr + 4 + m4]};
            uint32_t bll[2] = {Klo_s[kr + m4], Klo_s[kr + 4 + m4]};
            mma16816(s[j], aQh, bhh);
            mma16816(s[j], aQh, bll);
            mma16816(s[j], aQl, bhh);
        }
        if (any_mask) {
#pragma unroll
            for (int j = 0; j < 16; ++j) {
                float2 sv = *(const float2*)&sb[8 * j + 2 * m4];
                s[j][0] += sv.x; s[j][1] += sv.y;
                s[j][2] += sv.x; s[j][3] += sv.y;
            }
        }
        // ---- row max ----
        float mx0 = s[0][0], mx1 = s[0][2];
#pragma unroll
        for (int j = 0; j < 16; ++j) {
            mx0 = fmaxf(mx0, fmaxf(s[j][0], s[j][1]));
            mx1 = fmaxf(mx1, fmaxf(s[j][2], s[j][3]));
        }
        mx0 = fmaxf(mx0, __shfl_xor_sync(0xffffffffu, mx0, 1));
        mx0 = fmaxf(mx0, __shfl_xor_sync(0xffffffffu, mx0, 2));
        mx1 = fmaxf(mx1, __shfl_xor_sync(0xffffffffu, mx1, 1));
        mx1 = fmaxf(mx1, __shfl_xor_sync(0xffffffffu, mx1, 2));

        const float mn0 = fmaxf(m_run0, mx0);
        const float mn1 = fmaxf(m_run1, mx1);
        const float c0 = ex2f(m_run0 - mn0);
        const float c1 = ex2f(m_run1 - mn1);
        m_run0 = mn0; m_run1 = mn1;
        lsum0 *= c0; lsum1 *= c1;
#pragma unroll
        for (int n = 0; n < 2; ++n) {
            o[n][0] *= c0; o[n][1] *= c0;
            o[n][2] *= c1; o[n][3] *= c1;
        }
        // ---- exp + l ----
        float la0 = 0.f, la1 = 0.f;
#pragma unroll
        for (int j = 0; j < 16; ++j) {
            s[j][0] = ex2f(s[j][0] - mn0);
            s[j][1] = ex2f(s[j][1] - mn0);
            s[j][2] = ex2f(s[j][2] - mn1);
            s[j][3] = ex2f(s[j][3] - mn1);
            la0 += s[j][0] + s[j][1];
            la1 += s[j][2] + s[j][3];
        }
        lsum0 += la0; lsum1 += la1;

        // ---- PV: O += P·V (3-way split) ----
#pragma unroll
        for (int c = 0; c < 8; ++c) {
            uint32_t ah[4], al[4];
            split_pair(s[2 * c][0],     s[2 * c][1],     ah[0], al[0]);
            split_pair(s[2 * c][2],     s[2 * c][3],     ah[1], al[1]);
            split_pair(s[2 * c + 1][0], s[2 * c + 1][1], ah[2], al[2]);
            split_pair(s[2 * c + 1][2], s[2 * c + 1][3], ah[3], al[3]);
#pragma unroll
            for (int n = 0; n < 2; ++n) {
                const int vr = (8 * n + g) * VSTRIDE + 8 * c;
                uint32_t bhh[2] = {Vthi_s[vr + m4], Vthi_s[vr + 4 + m4]};
                uint32_t bll[2] = {Vtlo_s[vr + m4], Vtlo_s[vr + 4 + m4]};
                mma16816(o[n], ah, bhh);
                mma16816(o[n], al, bhh);
                mma16816(o[n], ah, bll);
            }
        }
        __syncthreads();
    }

    // ---- epilogue ----
    lsum0 += __shfl_xor_sync(0xffffffffu, lsum0, 1);
    lsum0 += __shfl_xor_sync(0xffffffffu, lsum0, 2);
    lsum1 += __shfl_xor_sync(0xffffffffu, lsum1, 1);
    lsum1 += __shfl_xor_sync(0xffffffffu, lsum1, 2);
    const float i0 = 1.f / lsum0, i1 = 1.f / lsum1;
    const int r0 = qt * 128 + warp * 16 + g;
#pragma unroll
    for (int n = 0; n < 2; ++n) {
        const int dim = h * D_K + 8 * n + 2 * m4;
        float2 lo = {o[n][0] * i0, o[n][1] * i0};
        float2 hi = {o[n][2] * i1, o[n][3] * i1};
        *(float2*)&g_attn[((size_t)b * N_SEQ + r0) * D_MODEL + dim]     = lo;
        *(float2*)&g_attn[((size_t)b * N_SEQ + r0 + 8) * D_MODEL + dim] = hi;
    }
}

// ===================== Kernel 3: FC projection + transpose ==================
__global__ __launch_bounds__(256) void fc_proj_kernel(
    const float* __restrict__ Wfc, const float* __restrict__ bfc,
    float* __restrict__ out)
{
    __shared__ float As[32 * 68];
    __shared__ float Wt[32 * 132];

    const int b  = blockIdx.y;
    const int n0 = blockIdx.x * 64;
    const int tid = threadIdx.x;
    const int tx = tid & 15, ty = tid >> 4;

    ull c2[4][4];
#pragma unroll
    for (int mm = 0; mm < 4; ++mm)
#pragma unroll
        for (int jp = 0; jp < 4; ++jp) c2[mm][jp] = 0ULL;

#pragma unroll 1
    for (int kc = 0; kc < 4; ++kc) {
        __syncthreads();
#pragma unroll
        for (int it = 0; it < 8; ++it) {
            int i = tid + it * 256;
            int m = i >> 5, dd = i & 31;
            As[dd * 68 + m] = g_attn[((size_t)b * N_SEQ + n0 + m) * D_MODEL + kc * 32 + dd];
        }
#pragma unroll
        for (int it = 0; it < 16; ++it) {
            int i = tid + it * 256;
            int j = i >> 5, dd = i & 31;
            Wt[dd * 132 + j] = Wfc[j * D_MODEL + kc * 32 + dd];
        }
        __syncthreads();

#pragma unroll 8
        for (int d = 0; d < 32; ++d) {
            float4 xv = *(const float4*)&As[d * 68 + tx * 4];
            ulonglong2 wA = *(const ulonglong2*)&Wt[d * 132 + ty * 8];
            ulonglong2 wB = *(const ulonglong2*)&Wt[d * 132 + ty * 8 + 4];
            ull x2[4] = {pack2(xv.x, xv.x), pack2(xv.y, xv.y),
                         pack2(xv.z, xv.z), pack2(xv.w, xv.w)};
#pragma unroll
            for (int mm = 0; mm < 4; ++mm) {
                c2[mm][0] = ffma2(x2[mm], wA.x, c2[mm][0]);
                c2[mm][1] = ffma2(x2[mm], wA.y, c2[mm][1]);
                c2[mm][2] = ffma2(x2[mm], wB.x, c2[mm][2]);
                c2[mm][3] = ffma2(x2[mm], wB.y, c2[mm][3]);
            }
        }
    }

    float cv[4][8];
#pragma unroll
    for (int mm = 0; mm < 4; ++mm)
#pragma unroll
        for (int jp = 0; jp < 4; ++jp) {
            float2 p = unpk2(c2[mm][jp]);
            cv[mm][2 * jp] = p.x; cv[mm][2 * jp + 1] = p.y;
        }

#pragma unroll
    for (int jj = 0; jj < 8; ++jj) {
        const int j = ty * 8 + jj;
        const float bias = bfc[j];
        float4 o = {cv[0][jj] + bias, cv[1][jj] + bias,
                    cv[2][jj] + bias, cv[3][jj] + bias};
        *(float4*)&out[((size_t)b * D_MODEL + j) * N_SEQ + n0 + tx * 4] = o;
    }
}

// ===========================================================================
extern "C" void kernel_launch(void* const* d_in, const int* in_sizes, int n_in,
                              void* d_out, int out_size)
{
    const float* x    = (const float*)d_in[0];
    const float* mask = (const float*)d_in[1];
    const float* Wq   = (const float*)d_in[2];
    const float* bq   = (const float*)d_in[3];
    const float* Wk   = (const float*)d_in[4];
    const float* bk   = (const float*)d_in[5];
    const float* Wv   = (const float*)d_in[6];
    const float* bv   = (const float*)d_in[7];
    const float* Wfc  = (const float*)d_in[8];
    const float* bfc  = (const float*)d_in[9];
    float* out = (float*)d_out;

    qkv_proj_kernel<<<dim3(N_SEQ / 64, BATCH, 3), 256>>>(x, Wq, bq, Wk, bk, Wv, bv);
    flash_attn_mma_kernel<<<dim3(N_SEQ / 128, N_HEAD, BATCH), 256>>>(mask);
    fc_proj_kernel<<<dim3(N_SEQ / 64, BATCH), 256>>>(Wfc, bfc, out);
}

// round 8
// speedup vs baseline: 3.3248x; 1.2094x over previous
#include <cuda_runtime.h>
#include <cuda_fp16.h>
#include <cstdint>

#define D_MODEL 128
#define N_SEQ   2048
#define BATCH   4
#define N_HEAD  8
#define D_K     16
#define NEG_INF -1e30f
#define LOG2E   1.4426950408889634f

typedef unsigned long long ull;
typedef unsigned short u16;

// ===================== f32x2 / misc helpers =================================
__device__ __forceinline__ ull pack2(float lo, float hi) {
    ull r; asm("mov.b64 %0, {%1,%2};" : "=l"(r) : "f"(lo), "f"(hi)); return r;
}
__device__ __forceinline__ float2 unpk2(ull a) {
    float2 r; asm("mov.b64 {%0,%1}, %2;" : "=f"(r.x), "=f"(r.y) : "l"(a)); return r;
}
__device__ __forceinline__ ull ffma2(ull a, ull b, ull c) {
    ull d; asm("fma.rn.f32x2 %0, %1, %2, %3;" : "=l"(d) : "l"(a), "l"(b), "l"(c)); return d;
}
__device__ __forceinline__ float ex2f(float x) {
    float y; asm("ex2.approx.f32 %0, %1;" : "=f"(y) : "f"(x)); return y;
}

// pack two f32 into fp16x2 (a -> low half, b -> high half)
__device__ __forceinline__ uint32_t packh2(float a, float b) {
    uint32_t r; asm("cvt.rn.f16x2.f32 %0, %1, %2;" : "=r"(r) : "f"(b), "f"(a)); return r;
}
// split a float pair into fp16x2 hi + fp16x2 lo (lo = residual)
__device__ __forceinline__ void split_pair_h(float a, float b, uint32_t& hi, uint32_t& lo) {
    asm("cvt.rn.f16x2.f32 %0, %1, %2;" : "=r"(hi) : "f"(b), "f"(a));
    float ha, hb;
    asm("{.reg .b16 x,y; mov.b32 {x,y}, %2; cvt.f32.f16 %0, x; cvt.f32.f16 %1, y;}"
        : "=f"(ha), "=f"(hb) : "r"(hi));
    float ra = a - ha, rb = b - hb;
    asm("cvt.rn.f16x2.f32 %0, %1, %2;" : "=r"(lo) : "f"(rb), "f"(ra));
}

// mma.sync m16n8k16 fp16 (row.col), fp32 accum
__device__ __forceinline__ void mma16816(float* c, const uint32_t* a, const uint32_t* b) {
    asm volatile("mma.sync.aligned.m16n8k16.row.col.f32.f16.f16.f32 "
        "{%0,%1,%2,%3}, {%4,%5,%6,%7}, {%8,%9}, {%0,%1,%2,%3};"
        : "+f"(c[0]), "+f"(c[1]), "+f"(c[2]), "+f"(c[3])
        : "r"(a[0]), "r"(a[1]), "r"(a[2]), "r"(a[3]), "r"(b[0]), "r"(b[1]));
}
// ldmatrix x4 (no trans)
__device__ __forceinline__ void ldmx4(uint32_t* r, uint32_t addr) {
    asm volatile("ldmatrix.sync.aligned.m8n8.x4.shared.b16 {%0,%1,%2,%3}, [%4];"
        : "=r"(r[0]), "=r"(r[1]), "=r"(r[2]), "=r"(r[3]) : "r"(addr));
}
__device__ __forceinline__ uint32_t smem_u32(const void* p) {
    uint32_t a;
    asm("{ .reg .u64 t; cvta.to.shared.u64 t, %1; cvt.u32.u64 %0, t; }" : "=r"(a) : "l"(p));
    return a;
}

// ===================== scratch ==============================================
// pre-split fp16 tensors, head-blocked layouts. Q/K: [bh][n][16]  V^T: [bh][16][N]
__device__ u16 g_qhi[32 * N_SEQ * 16], g_qlo[32 * N_SEQ * 16];
__device__ u16 g_khi[32 * N_SEQ * 16], g_klo[32 * N_SEQ * 16];
__device__ u16 g_vthi[32 * 16 * N_SEQ], g_vtlo[32 * 16 * N_SEQ];
__device__ float g_attn[BATCH * N_SEQ * D_MODEL];

// ===================== Kernel 1: QKV projection + fp16 split ================
__global__ __launch_bounds__(256) void qkv_proj_kernel(
    const float* __restrict__ x,
    const float* __restrict__ Wq, const float* __restrict__ bq,
    const float* __restrict__ Wk, const float* __restrict__ bk,
    const float* __restrict__ Wv, const float* __restrict__ bv)
{
    __shared__ float Xs[32 * 64];
    __shared__ float Wt[32 * 132];

    const int b  = blockIdx.y;
    const int n0 = blockIdx.x * 64;
    const int w  = blockIdx.z;
    const int tid = threadIdx.x;

    const float* W    = (w == 0) ? Wq : (w == 1) ? Wk : Wv;
    const float* bias = (w == 0) ? bq : (w == 1) ? bk : bv;

    const int tx = tid & 15, ty = tid >> 4;

    ull c2[4][4];
#pragma unroll
    for (int mm = 0; mm < 4; ++mm)
#pragma unroll
        for (int jp = 0; jp < 4; ++jp) c2[mm][jp] = 0ULL;

#pragma unroll 1
    for (int kc = 0; kc < 4; ++kc) {
        __syncthreads();
#pragma unroll
        for (int it = 0; it < 8; ++it) {
            int i = tid + it * 256;
            int dd = i >> 6, m = i & 63;
            Xs[i] = x[((size_t)b * D_MODEL + kc * 32 + dd) * N_SEQ + n0 + m];
        }
#pragma unroll
        for (int it = 0; it < 16; ++it) {
            int i = tid + it * 256;
            int j = i >> 5, dd = i & 31;
            Wt[dd * 132 + j] = W[j * D_MODEL + kc * 32 + dd];
        }
        __syncthreads();

#pragma unroll 8
        for (int d = 0; d < 32; ++d) {
            float4 xv = *(const float4*)&Xs[d * 64 + tx * 4];
            ulonglong2 wA = *(const ulonglong2*)&Wt[d * 132 + ty * 8];
            ulonglong2 wB = *(const ulonglong2*)&Wt[d * 132 + ty * 8 + 4];
            ull x2[4] = {pack2(xv.x, xv.x), pack2(xv.y, xv.y),
                         pack2(xv.z, xv.z), pack2(xv.w, xv.w)};
#pragma unroll
            for (int mm = 0; mm < 4; ++mm) {
                c2[mm][0] = ffma2(x2[mm], wA.x, c2[mm][0]);
                c2[mm][1] = ffma2(x2[mm], wA.y, c2[mm][1]);
                c2[mm][2] = ffma2(x2[mm], wB.x, c2[mm][2]);
                c2[mm][3] = ffma2(x2[mm], wB.y, c2[mm][3]);
            }
        }
    }

    float bi[8];
#pragma unroll
    for (int jj = 0; jj < 8; ++jj) bi[jj] = bias[ty * 8 + jj];

    const int h    = ty >> 1;
    const int dblk = (ty & 1) * 8;
    const int bh   = b * N_HEAD + h;
    const float qscale = 0.08838834764831843f * LOG2E;

    float cv[4][8];
#pragma unroll
    for (int mm = 0; mm < 4; ++mm)
#pragma unroll
        for (int jp = 0; jp < 4; ++jp) {
            float2 p = unpk2(c2[mm][jp]);
            cv[mm][2 * jp] = p.x + bi[2 * jp];
            cv[mm][2 * jp + 1] = p.y + bi[2 * jp + 1];
        }

    if (w == 2) {
        uint32_t vh[4][4], vl[4][4];
#pragma unroll
        for (int mm = 0; mm < 4; ++mm)
#pragma unroll
            for (int jp = 0; jp < 4; ++jp)
                split_pair_h(cv[mm][2 * jp], cv[mm][2 * jp + 1], vh[mm][jp], vl[mm][jp]);
#pragma unroll
        for (int jj = 0; jj < 8; ++jj) {
            const int jp = jj >> 1, sh = (jj & 1) * 16;
            ushort4 oh = {(u16)(vh[0][jp] >> sh), (u16)(vh[1][jp] >> sh),
                          (u16)(vh[2][jp] >> sh), (u16)(vh[3][jp] >> sh)};
            ushort4 ol = {(u16)(vl[0][jp] >> sh), (u16)(vl[1][jp] >> sh),
                          (u16)(vl[2][jp] >> sh), (u16)(vl[3][jp] >> sh)};
            size_t base = ((size_t)bh * 16 + dblk + jj) * N_SEQ + n0 + tx * 4;
            *(ushort4*)&g_vthi[base] = oh;
            *(ushort4*)&g_vtlo[base] = ol;
        }
    } else {
        u16* Ohi = (w == 0) ? g_qhi : g_khi;
        u16* Olo = (w == 0) ? g_qlo : g_klo;
        const float sc = (w == 0) ? qscale : 1.f;
#pragma unroll
        for (int mm = 0; mm < 4; ++mm) {
            uint32_t hi[4], lo[4];
#pragma unroll
            for (int jp = 0; jp < 4; ++jp)
                split_pair_h(cv[mm][2 * jp] * sc, cv[mm][2 * jp + 1] * sc, hi[jp], lo[jp]);
            size_t base = ((size_t)bh * N_SEQ + n0 + tx * 4 + mm) * 16 + dblk;
            *(uint4*)&Ohi[base] = make_uint4(hi[0], hi[1], hi[2], hi[3]);
            *(uint4*)&Olo[base] = make_uint4(lo[0], lo[1], lo[2], lo[3]);
        }
    }
}

// ===================== Kernel 2: mma.sync flash attention ===================
// 256 threads = 8 warps; warp owns one m16 q-tile. ldmatrix fragments,
// fp16 splits (P unsplit), l folded into PV via a ones-row n-tile.
#define KSTRIDE 12   // dwords per K row (48B) — conflict-free for ldmatrix
#define VSTRIDE 68   // dwords per Vt row (272B) — conflict-free for ldmatrix

__global__ __launch_bounds__(256, 2) void flash_attn_mma_kernel(
    const float* __restrict__ mask)
{
    __shared__ __align__(16) uint32_t Khi_s[128 * KSTRIDE], Klo_s[128 * KSTRIDE];
    __shared__ __align__(16) uint32_t Vthi_s[24 * VSTRIDE], Vtlo_s[16 * VSTRIDE];
    __shared__ float sb[128];

    const int qt = blockIdx.x, h = blockIdx.y, b = blockIdx.z;
    const int bh = b * N_HEAD + h;
    const int tid  = threadIdx.x;
    const int warp = tid >> 5;
    const int lane = tid & 31;
    const int g  = lane >> 2;
    const int m4 = lane & 3;
    const int mat = lane >> 3, rin = lane & 7;

    // --- Q fragments straight from global (pre-scaled, pre-split fp16) ---
    uint32_t aQh[4], aQl[4];
    {
        const uint32_t* qh = (const uint32_t*)g_qhi + (size_t)bh * N_SEQ * 8;
        const uint32_t* ql = (const uint32_t*)g_qlo + (size_t)bh * N_SEQ * 8;
        const int r0 = qt * 128 + warp * 16 + g, r1 = r0 + 8;
        aQh[0] = qh[r0 * 8 + m4];     aQh[1] = qh[r1 * 8 + m4];
        aQh[2] = qh[r0 * 8 + 4 + m4]; aQh[3] = qh[r1 * 8 + 4 + m4];
        aQl[0] = ql[r0 * 8 + m4];     aQl[1] = ql[r1 * 8 + m4];
        aQl[2] = ql[r0 * 8 + 4 + m4]; aQl[3] = ql[r1 * 8 + 4 + m4];
    }

    // --- ldmatrix per-lane base addresses ---
    const uint32_t koff = (uint32_t)((((mat >> 1) * 8 + rin) * KSTRIDE + (mat & 1) * 4) * 4);
    const uint32_t kAddrHi = smem_u32(Khi_s) + koff;
    const uint32_t kAddrLo = smem_u32(Klo_s) + koff;
    const uint32_t voff = (uint32_t)(rin * VSTRIDE * 4 + mat * 16);
    const uint32_t vAddrHi = smem_u32(Vthi_s) + voff;
    const uint32_t vAddrLo = smem_u32(Vtlo_s) + voff;

    // --- ones row (dim 16) + zero rows 17-23 of Vthi, written once ---
    for (int i = tid; i < 8 * VSTRIDE; i += 256) {
        int r = i / VSTRIDE;
        Vthi_s[(16 + r) * VSTRIDE + (i % VSTRIDE)] = (r == 0) ? 0x3C003C00u : 0u;
    }

    // o[0..1] = output dims, o[2] col16 = l
    float o[3][4];
#pragma unroll
    for (int n = 0; n < 3; ++n)
#pragma unroll
        for (int i = 0; i < 4; ++i) o[n][i] = 0.f;
    float m_run0 = -1e30f, m_run1 = -1e30f;

#pragma unroll 1
    for (int t = 0; t < 16; ++t) {
        // --- stage K (tid<128) / Vt (tid>=128), pre-split fp16 ---
        int pred = 0;
        if (tid < 128) {
            const size_t rb = ((size_t)bh * N_SEQ + t * 128 + tid) * 16;
            const uint4* kh = (const uint4*)&g_khi[rb];
            const uint4* kl = (const uint4*)&g_klo[rb];
            uint4 h0 = kh[0], h1 = kh[1], l0 = kl[0], l1 = kl[1];
            *(uint4*)&Khi_s[tid * KSTRIDE]     = h0;
            *(uint4*)&Khi_s[tid * KSTRIDE + 4] = h1;
            *(uint4*)&Klo_s[tid * KSTRIDE]     = l0;
            *(uint4*)&Klo_s[tid * KSTRIDE + 4] = l1;
            float mv = mask[(size_t)b * N_SEQ + t * 128 + tid];
            float bias = (1.f - mv) * (NEG_INF * LOG2E);
            sb[tid] = bias;
            pred = (bias != 0.f);
        } else {
            const int t2 = tid - 128;
            const int row = t2 >> 3, seg = t2 & 7;
            const size_t sbase = ((size_t)bh * 16 + row) * N_SEQ + t * 128 + seg * 16;
            const uint4* vh = (const uint4*)&g_vthi[sbase];
            const uint4* vl = (const uint4*)&g_vtlo[sbase];
            uint4 h0 = vh[0], h1 = vh[1], l0 = vl[0], l1 = vl[1];
            *(uint4*)&Vthi_s[row * VSTRIDE + seg * 8]     = h0;
            *(uint4*)&Vthi_s[row * VSTRIDE + seg * 8 + 4] = h1;
            *(uint4*)&Vtlo_s[row * VSTRIDE + seg * 8]     = l0;
            *(uint4*)&Vtlo_s[row * VSTRIDE + seg * 8 + 4] = l1;
        }
        const int any_mask = __syncthreads_or(pred);

        // --- two 64-key halves ---
#pragma unroll
        for (int hf = 0; hf < 2; ++hf) {
            float s[8][4];
            // ---- S = Q·K^T (fp16 3-way split), ldmatrix B-frags ----
            uint32_t kh = kAddrHi + (uint32_t)(hf * 64 * KSTRIDE * 4);
            uint32_t kl = kAddrLo + (uint32_t)(hf * 64 * KSTRIDE * 4);
#pragma unroll
            for (int i = 0; i < 4; ++i) {
                uint32_t bh4[4], bl4[4];
                ldmx4(bh4, kh); ldmx4(bl4, kl);
                kh += 16 * KSTRIDE * 4; kl += 16 * KSTRIDE * 4;
#pragma unroll
                for (int q2 = 0; q2 < 2; ++q2) {
                    float* sj = s[2 * i + q2];
                    sj[0] = sj[1] = sj[2] = sj[3] = 0.f;
                    mma16816(sj, aQh, bh4 + 2 * q2);
                    mma16816(sj, aQh, bl4 + 2 * q2);
                    mma16816(sj, aQl, bh4 + 2 * q2);
                }
            }
            if (any_mask) {
#pragma unroll
                for (int j = 0; j < 8; ++j) {
                    float2 sv = *(const float2*)&sb[hf * 64 + 8 * j + 2 * m4];
                    s[j][0] += sv.x; s[j][1] += sv.y;
                    s[j][2] += sv.x; s[j][3] += sv.y;
                }
            }
            // ---- row max ----
            float mx0 = fmaxf(s[0][0], s[0][1]), mx1 = fmaxf(s[0][2], s[0][3]);
#pragma unroll
            for (int j = 1; j < 8; ++j) {
                mx0 = fmaxf(mx0, fmaxf(s[j][0], s[j][1]));
                mx1 = fmaxf(mx1, fmaxf(s[j][2], s[j][3]));
            }
            mx0 = fmaxf(mx0, __shfl_xor_sync(0xffffffffu, mx0, 1));
            mx0 = fmaxf(mx0, __shfl_xor_sync(0xffffffffu, mx0, 2));
            mx1 = fmaxf(mx1, __shfl_xor_sync(0xffffffffu, mx1, 1));
            mx1 = fmaxf(mx1, __shfl_xor_sync(0xffffffffu, mx1, 2));

            const float mn0 = fmaxf(m_run0, mx0);
            const float mn1 = fmaxf(m_run1, mx1);
            const float c0 = ex2f(m_run0 - mn0);
            const float c1 = ex2f(m_run1 - mn1);
            m_run0 = mn0; m_run1 = mn1;
#pragma unroll
            for (int n = 0; n < 3; ++n) {
                o[n][0] *= c0; o[n][1] *= c0;
                o[n][2] *= c1; o[n][3] *= c1;
            }
            // ---- exp ----
#pragma unroll
            for (int j = 0; j < 8; ++j) {
                s[j][0] = ex2f(s[j][0] - mn0);
                s[j][1] = ex2f(s[j][1] - mn0);
                s[j][2] = ex2f(s[j][2] - mn1);
                s[j][3] = ex2f(s[j][3] - mn1);
            }
            // ---- PV (+ ones column for l): O += P·[V|1] ----
#pragma unroll
            for (int cc = 0; cc < 2; ++cc) {
                const int cp = 2 * hf + cc;           // 32-key group
                uint32_t vh0[4], vh1[4], vh2[4], vl0[4], vl1[4];
                const uint32_t va = vAddrHi + (uint32_t)(cp * 64);
                const uint32_t vb = vAddrLo + (uint32_t)(cp * 64);
                ldmx4(vh0, va);
                ldmx4(vh1, va + 8 * VSTRIDE * 4);
                ldmx4(vh2, va + 16 * VSTRIDE * 4);
                ldmx4(vl0, vb);
                ldmx4(vl1, vb + 8 * VSTRIDE * 4);
#pragma unroll
                for (int q2 = 0; q2 < 2; ++q2) {
                    const int c = 2 * cc + q2;        // 16-key k-tile within half
                    uint32_t a[4] = {
                        packh2(s[2 * c][0],     s[2 * c][1]),
                        packh2(s[2 * c][2],     s[2 * c][3]),
                        packh2(s[2 * c + 1][0], s[2 * c + 1][1]),
                        packh2(s[2 * c + 1][2], s[2 * c + 1][3])};
                    mma16816(o[0], a, vh0 + 2 * q2);
                    mma16816(o[1], a, vh1 + 2 * q2);
                    mma16816(o[2], a, vh2 + 2 * q2);
                    mma16816(o[0], a, vl0 + 2 * q2);
                    mma16816(o[1], a, vl1 + 2 * q2);
                }
            }
        }
        __syncthreads();
    }

    // ---- epilogue: l lives in col 16 (m4==0 lane of each quad) ----
    const float l0 = __shfl_sync(0xffffffffu, o[2][0], lane & ~3);
    const float l1 = __shfl_sync(0xffffffffu, o[2][2], lane & ~3);
    const float i0 = 1.f / l0, i1 = 1.f / l1;
    const int r0 = qt * 128 + warp * 16 + g;
#pragma unroll
    for (int n = 0; n < 2; ++n) {
        const int dim = h * D_K + 8 * n + 2 * m4;
        float2 lo = {o[n][0] * i0, o[n][1] * i0};
        float2 hi = {o[n][2] * i1, o[n][3] * i1};
        *(float2*)&g_attn[((size_t)b * N_SEQ + r0) * D_MODEL + dim]     = lo;
        *(float2*)&g_attn[((size_t)b * N_SEQ + r0 + 8) * D_MODEL + dim] = hi;
    }
}

// ===================== Kernel 3: FC projection + transpose ==================
__global__ __launch_bounds__(256) void fc_proj_kernel(
    const float* __restrict__ Wfc, const float* __restrict__ bfc,
    float* __restrict__ out)
{
    __shared__ float As[32 * 68];
    __shared__ float Wt[32 * 132];

    const int b  = blockIdx.y;
    const int n0 = blockIdx.x * 64;
    const int tid = threadIdx.x;
    const int tx = tid & 15, ty = tid >> 4;

    ull c2[4][4];
#pragma unroll
    for (int mm = 0; mm < 4; ++mm)
#pragma unroll
        for (int jp = 0; jp < 4; ++jp) c2[mm][jp] = 0ULL;

#pragma unroll 1
    for (int kc = 0; kc < 4; ++kc) {
        __syncthreads();
#pragma unroll
        for (int it = 0; it < 8; ++it) {
            int i = tid + it * 256;
            int m = i >> 5, dd = i & 31;
            As[dd * 68 + m] = g_attn[((size_t)b * N_SEQ + n0 + m) * D_MODEL + kc * 32 + dd];
        }
#pragma unroll
        for (int it = 0; it < 16; ++it) {
            int i = tid + it * 256;
            int j = i >> 5, dd = i & 31;
            Wt[dd * 132 + j] = Wfc[j * D_MODEL + kc * 32 + dd];
        }
        __syncthreads();

#pragma unroll 8
        for (int d = 0; d < 32; ++d) {
            float4 xv = *(const float4*)&As[d * 68 + tx * 4];
            ulonglong2 wA = *(const ulonglong2*)&Wt[d * 132 + ty * 8];
            ulonglong2 wB = *(const ulonglong2*)&Wt[d * 132 + ty * 8 + 4];
            ull x2[4] = {pack2(xv.x, xv.x), pack2(xv.y, xv.y),
                         pack2(xv.z, xv.z), pack2(xv.w, xv.w)};
#pragma unroll
            for (int mm = 0; mm < 4; ++mm) {
                c2[mm][0] = ffma2(x2[mm], wA.x, c2[mm][0]);
                c2[mm][1] = ffma2(x2[mm], wA.y, c2[mm][1]);
                c2[mm][2] = ffma2(x2[mm], wB.x, c2[mm][2]);
                c2[mm][3] = ffma2(x2[mm], wB.y, c2[mm][3]);
            }
        }
    }

    float cv[4][8];
#pragma unroll
    for (int mm = 0; mm < 4; ++mm)
#pragma unroll
        for (int jp = 0; jp < 4; ++jp) {
            float2 p = unpk2(c2[mm][jp]);
            cv[mm][2 * jp] = p.x; cv[mm][2 * jp + 1] = p.y;
        }

#pragma unroll
    for (int jj = 0; jj < 8; ++jj) {
        const int j = ty * 8 + jj;
        const float bias = bfc[j];
        float4 o = {cv[0][jj] + bias, cv[1][jj] + bias,
                    cv[2][jj] + bias, cv[3][jj] + bias};
        *(float4*)&out[((size_t)b * D_MODEL + j) * N_SEQ + n0 + tx * 4] = o;
    }
}

// ===========================================================================
extern "C" void kernel_launch(void* const* d_in, const int* in_sizes, int n_in,
                              void* d_out, int out_size)
{
    const float* x    = (const float*)d_in[0];
    const float* mask = (const float*)d_in[1];
    const float* Wq   = (const float*)d_in[2];
    const float* bq   = (const float*)d_in[3];
    const float* Wk   = (const float*)d_in[4];
    const float* bk   = (const float*)d_in[5];
    const float* Wv   = (const float*)d_in[6];
    const float* bv   = (const float*)d_in[7];
    const float* Wfc  = (const float*)d_in[8];
    const float* bfc  = (const float*)d_in[9];
    float* out = (float*)d_out;

    qkv_proj_kernel<<<dim3(N_SEQ / 64, BATCH, 3), 256>>>(x, Wq, bq, Wk, bk, Wv, bv);
    flash_attn_mma_kernel<<<dim3(N_SEQ / 128, N_HEAD, BATCH), 256>>>(mask);
    fc_proj_kernel<<<dim3(N_SEQ / 64, BATCH), 256>>>(Wfc, bfc, out);
}

// round 10
// speedup vs baseline: 3.8732x; 1.1650x over previous
#include <cuda_runtime.h>
#include <cuda_fp16.h>
#include <cstdint>

#define D_MODEL 128
#define N_SEQ   2048
#define BATCH   4
#define N_HEAD  8
#define D_K     16
#define NEG_INF -1e30f
#define LOG2E   1.4426950408889634f

typedef unsigned long long ull;
typedef unsigned short u16;

// ===================== f32x2 / misc helpers =================================
__device__ __forceinline__ ull pack2(float lo, float hi) {
    ull r; asm("mov.b64 %0, {%1,%2};" : "=l"(r) : "f"(lo), "f"(hi)); return r;
}
__device__ __forceinline__ float2 unpk2(ull a) {
    float2 r; asm("mov.b64 {%0,%1}, %2;" : "=f"(r.x), "=f"(r.y) : "l"(a)); return r;
}
__device__ __forceinline__ ull ffma2(ull a, ull b, ull c) {
    ull d; asm("fma.rn.f32x2 %0, %1, %2, %3;" : "=l"(d) : "l"(a), "l"(b), "l"(c)); return d;
}
__device__ __forceinline__ float ex2f(float x) {
    float y; asm("ex2.approx.f32 %0, %1;" : "=f"(y) : "f"(x)); return y;
}

// pack two f32 into fp16x2 (a -> low half, b -> high half)
__device__ __forceinline__ uint32_t packh2(float a, float b) {
    uint32_t r; asm("cvt.rn.f16x2.f32 %0, %1, %2;" : "=r"(r) : "f"(b), "f"(a)); return r;
}
// split a float pair into fp16x2 hi + fp16x2 lo (lo = residual)
__device__ __forceinline__ void split_pair_h(float a, float b, uint32_t& hi, uint32_t& lo) {
    asm("cvt.rn.f16x2.f32 %0, %1, %2;" : "=r"(hi) : "f"(b), "f"(a));
    float ha, hb;
    asm("{.reg .b16 x,y; mov.b32 {x,y}, %2; cvt.f32.f16 %0, x; cvt.f32.f16 %1, y;}"
        : "=f"(ha), "=f"(hb) : "r"(hi));
    float ra = a - ha, rb = b - hb;
    asm("cvt.rn.f16x2.f32 %0, %1, %2;" : "=r"(lo) : "f"(rb), "f"(ra));
}

// mma.sync m16n8k16 fp16 (row.col), fp32 accum
__device__ __forceinline__ void mma16816(float* c, const uint32_t* a, const uint32_t* b) {
    asm volatile("mma.sync.aligned.m16n8k16.row.col.f32.f16.f16.f32 "
        "{%0,%1,%2,%3}, {%4,%5,%6,%7}, {%8,%9}, {%0,%1,%2,%3};"
        : "+f"(c[0]), "+f"(c[1]), "+f"(c[2]), "+f"(c[3])
        : "r"(a[0]), "r"(a[1]), "r"(a[2]), "r"(a[3]), "r"(b[0]), "r"(b[1]));
}
// ldmatrix x4 (no trans)
__device__ __forceinline__ void ldmx4(uint32_t* r, uint32_t addr) {
    asm volatile("ldmatrix.sync.aligned.m8n8.x4.shared.b16 {%0,%1,%2,%3}, [%4];"
        : "=r"(r[0]), "=r"(r[1]), "=r"(r[2]), "=r"(r[3]) : "r"(addr));
}
__device__ __forceinline__ uint32_t smem_u32(const void* p) {
    uint32_t a;
    asm("{ .reg .u64 t; cvta.to.shared.u64 t, %1; cvt.u32.u64 %0, t; }" : "=r"(a) : "l"(p));
    return a;
}

// ===================== scratch ==============================================
// fp16 tensors, head-blocked layouts. Q/K: [bh][n][16]  V^T: [bh][16][N]
// Q and V: plain fp16; K: hi + lo residual split.
__device__ u16 g_qh[32 * N_SEQ * 16];
__device__ u16 g_khi[32 * N_SEQ * 16], g_klo[32 * N_SEQ * 16];
__device__ u16 g_vth[32 * 16 * N_SEQ];
__device__ float g_attn[BATCH * N_SEQ * D_MODEL];

// ===================== Kernel 1: QKV projection + fp16 pack/split ===========
__global__ __launch_bounds__(256) void qkv_proj_kernel(
    const float* __restrict__ x,
    const float* __restrict__ Wq, const float* __restrict__ bq,
    const float* __restrict__ Wk, const float* __restrict__ bk,
    const float* __restrict__ Wv, const float* __restrict__ bv)
{
    __shared__ float Xs[32 * 64];
    __shared__ float Wt[32 * 132];

    const int b  = blockIdx.y;
    const int n0 = blockIdx.x * 64;
    const int w  = blockIdx.z;
    const int tid = threadIdx.x;

    const float* W    = (w == 0) ? Wq : (w == 1) ? Wk : Wv;
    const float* bias = (w == 0) ? bq : (w == 1) ? bk : bv;

    const int tx = tid & 15, ty = tid >> 4;

    ull c2[4][4];
#pragma unroll
    for (int mm = 0; mm < 4; ++mm)
#pragma unroll
        for (int jp = 0; jp < 4; ++jp) c2[mm][jp] = 0ULL;

#pragma unroll 1
    for (int kc = 0; kc < 4; ++kc) {
        __syncthreads();
#pragma unroll
        for (int it = 0; it < 8; ++it) {
            int i = tid + it * 256;
            int dd = i >> 6, m = i & 63;
            Xs[i] = x[((size_t)b * D_MODEL + kc * 32 + dd) * N_SEQ + n0 + m];
        }
#pragma unroll
        for (int it = 0; it < 16; ++it) {
            int i = tid + it * 256;
            int j = i >> 5, dd = i & 31;
            Wt[dd * 132 + j] = W[j * D_MODEL + kc * 32 + dd];
        }
        __syncthreads();

#pragma unroll 8
        for (int d = 0; d < 32; ++d) {
            float4 xv = *(const float4*)&Xs[d * 64 + tx * 4];
            ulonglong2 wA = *(const ulonglong2*)&Wt[d * 132 + ty * 8];
            ulonglong2 wB = *(const ulonglong2*)&Wt[d * 132 + ty * 8 + 4];
            ull x2[4] = {pack2(xv.x, xv.x), pack2(xv.y, xv.y),
                         pack2(xv.z, xv.z), pack2(xv.w, xv.w)};
#pragma unroll
            for (int mm = 0; mm < 4; ++mm) {
                c2[mm][0] = ffma2(x2[mm], wA.x, c2[mm][0]);
                c2[mm][1] = ffma2(x2[mm], wA.y, c2[mm][1]);
                c2[mm][2] = ffma2(x2[mm], wB.x, c2[mm][2]);
                c2[mm][3] = ffma2(x2[mm], wB.y, c2[mm][3]);
            }
        }
    }

    float bi[8];
#pragma unroll
    for (int jj = 0; jj < 8; ++jj) bi[jj] = bias[ty * 8 + jj];

    const int h    = ty >> 1;
    const int dblk = (ty & 1) * 8;
    const int bh   = b * N_HEAD + h;
    const float qscale = 0.08838834764831843f * LOG2E;

    float cv[4][8];
#pragma unroll
    for (int mm = 0; mm < 4; ++mm)
#pragma unroll
        for (int jp = 0; jp < 4; ++jp) {
            float2 p = unpk2(c2[mm][jp]);
            cv[mm][2 * jp] = p.x + bi[2 * jp];
            cv[mm][2 * jp + 1] = p.y + bi[2 * jp + 1];
        }

    if (w == 2) {
        // V: plain fp16, transposed [bh][d][n]
        uint32_t vh[4][4];
#pragma unroll
        for (int mm = 0; mm < 4; ++mm)
#pragma unroll
            for (int jp = 0; jp < 4; ++jp)
                vh[mm][jp] = packh2(cv[mm][2 * jp], cv[mm][2 * jp + 1]);
#pragma unroll
        for (int jj = 0; jj < 8; ++jj) {
            const int jp = jj >> 1, sh = (jj & 1) * 16;
            ushort4 oh = {(u16)(vh[0][jp] >> sh), (u16)(vh[1][jp] >> sh),
                          (u16)(vh[2][jp] >> sh), (u16)(vh[3][jp] >> sh)};
            size_t base = ((size_t)bh * 16 + dblk + jj) * N_SEQ + n0 + tx * 4;
            *(ushort4*)&g_vth[base] = oh;
        }
    } else if (w == 0) {
        // Q: plain fp16, scale folded
#pragma unroll
        for (int mm = 0; mm < 4; ++mm) {
            uint32_t hi[4];
#pragma unroll
            for (int jp = 0; jp < 4; ++jp)
                hi[jp] = packh2(cv[mm][2 * jp] * qscale, cv[mm][2 * jp + 1] * qscale);
            size_t base = ((size_t)bh * N_SEQ + n0 + tx * 4 + mm) * 16 + dblk;
            *(uint4*)&g_qh[base] = make_uint4(hi[0], hi[1], hi[2], hi[3]);
        }
    } else {
        // K: hi/lo split
#pragma unroll
        for (int mm = 0; mm < 4; ++mm) {
            uint32_t hi[4], lo[4];
#pragma unroll
            for (int jp = 0; jp < 4; ++jp)
                split_pair_h(cv[mm][2 * jp], cv[mm][2 * jp + 1], hi[jp], lo[jp]);
            size_t base = ((size_t)bh * N_SEQ + n0 + tx * 4 + mm) * 16 + dblk;
            *(uint4*)&g_khi[base] = make_uint4(hi[0], hi[1], hi[2], hi[3]);
            *(uint4*)&g_klo[base] = make_uint4(lo[0], lo[1], lo[2], lo[3]);
        }
    }
}

// ===================== Kernel 2: mma.sync flash attention ===================
// 256 threads = 8 warps; warp owns one m16 q-tile. Q,V plain fp16; K split.
#define KSTRIDE 12   // dwords per K row (48B) — conflict-free for ldmatrix
#define VSTRIDE 68   // dwords per Vt row (272B) — conflict-free for ldmatrix

__global__ __launch_bounds__(256, 2) void flash_attn_mma_kernel(
    const float* __restrict__ mask)
{
    __shared__ __align__(16) uint32_t Khi_s[128 * KSTRIDE], Klo_s[128 * KSTRIDE];
    __shared__ __align__(16) uint32_t Vth_s[24 * VSTRIDE];
    __shared__ float sb[128];

    const int qt = blockIdx.x, h = blockIdx.y, b = blockIdx.z;
    const int bh = b * N_HEAD + h;
    const int tid  = threadIdx.x;
    const int warp = tid >> 5;
    const int lane = tid & 31;
    const int g  = lane >> 2;
    const int m4 = lane & 3;
    const int mat = lane >> 3, rin = lane & 7;

    // --- Q fragments straight from global (pre-scaled fp16) ---
    uint32_t aQ[4];
    {
        const uint32_t* qh = (const uint32_t*)g_qh + (size_t)bh * N_SEQ * 8;
        const int r0 = qt * 128 + warp * 16 + g, r1 = r0 + 8;
        aQ[0] = qh[r0 * 8 + m4];     aQ[1] = qh[r1 * 8 + m4];
        aQ[2] = qh[r0 * 8 + 4 + m4]; aQ[3] = qh[r1 * 8 + 4 + m4];
    }

    // --- ldmatrix per-lane base addresses ---
    const uint32_t koff = (uint32_t)((((mat >> 1) * 8 + rin) * KSTRIDE + (mat & 1) * 4) * 4);
    const uint32_t kAddrHi = smem_u32(Khi_s) + koff;
    const uint32_t kAddrLo = smem_u32(Klo_s) + koff;
    const uint32_t voff = (uint32_t)(rin * VSTRIDE * 4 + mat * 16);
    const uint32_t vAddr = smem_u32(Vth_s) + voff;

    // --- ones row (dim 16) + zero rows 17-23, written once ---
    for (int i = tid; i < 8 * VSTRIDE; i += 256) {
        int r = i / VSTRIDE;
        Vth_s[(16 + r) * VSTRIDE + (i % VSTRIDE)] = (r == 0) ? 0x3C003C00u : 0u;
    }

    // o[0..1] = output dims, o[2] col16 = l
    float o[3][4];
#pragma unroll
    for (int n = 0; n < 3; ++n)
#pragma unroll
        for (int i = 0; i < 4; ++i) o[n][i] = 0.f;
    float m_run0 = -1e30f, m_run1 = -1e30f;

#pragma unroll 1
    for (int t = 0; t < 16; ++t) {
        // --- stage K (tid<128) / Vt (tid>=128) ---
        int pred = 0;
        if (tid < 128) {
            const size_t rb = ((size_t)bh * N_SEQ + t * 128 + tid) * 16;
            const uint4* kh = (const uint4*)&g_khi[rb];
            const uint4* kl = (const uint4*)&g_klo[rb];
            uint4 h0 = kh[0], h1 = kh[1], l0 = kl[0], l1 = kl[1];
            *(uint4*)&Khi_s[tid * KSTRIDE]     = h0;
            *(uint4*)&Khi_s[tid * KSTRIDE + 4] = h1;
            *(uint4*)&Klo_s[tid * KSTRIDE]     = l0;
            *(uint4*)&Klo_s[tid * KSTRIDE + 4] = l1;
            float mv = mask[(size_t)b * N_SEQ + t * 128 + tid];
            float bias = (1.f - mv) * (NEG_INF * LOG2E);
            sb[tid] = bias;
            pred = (bias != 0.f);
        } else {
            const int t2 = tid - 128;
            const int row = t2 >> 3, seg = t2 & 7;
            const size_t sbase = ((size_t)bh * 16 + row) * N_SEQ + t * 128 + seg * 16;
            const uint4* vh = (const uint4*)&g_vth[sbase];
            uint4 h0 = vh[0], h1 = vh[1];
            *(uint4*)&Vth_s[row * VSTRIDE + seg * 8]     = h0;
            *(uint4*)&Vth_s[row * VSTRIDE + seg * 8 + 4] = h1;
        }
        const int any_mask = __syncthreads_or(pred);

        // --- two 64-key halves ---
#pragma unroll
        for (int hf = 0; hf < 2; ++hf) {
            float s[8][4];
            // ---- S = Qhi·(Khi+Klo), ldmatrix B-frags ----
            uint32_t kh = kAddrHi + (uint32_t)(hf * 64 * KSTRIDE * 4);
            uint32_t kl = kAddrLo + (uint32_t)(hf * 64 * KSTRIDE * 4);
#pragma unroll
            for (int i = 0; i < 4; ++i) {
                uint32_t bh4[4], bl4[4];
                ldmx4(bh4, kh); ldmx4(bl4, kl);
                kh += 16 * KSTRIDE * 4; kl += 16 * KSTRIDE * 4;
#pragma unroll
                for (int q2 = 0; q2 < 2; ++q2) {
                    float* sj = s[2 * i + q2];
                    sj[0] = sj[1] = sj[2] = sj[3] = 0.f;
                    mma16816(sj, aQ, bh4 + 2 * q2);
                    mma16816(sj, aQ, bl4 + 2 * q2);
                }
            }
            if (any_mask) {
#pragma unroll
                for (int j = 0; j < 8; ++j) {
                    float2 sv = *(const float2*)&sb[hf * 64 + 8 * j + 2 * m4];
                    s[j][0] += sv.x; s[j][1] += sv.y;
                    s[j][2] += sv.x; s[j][3] += sv.y;
                }
            }
            // ---- row max ----
            float mx0 = fmaxf(s[0][0], s[0][1]), mx1 = fmaxf(s[0][2], s[0][3]);
#pragma unroll
            for (int j = 1; j < 8; ++j) {
                mx0 = fmaxf(mx0, fmaxf(s[j][0], s[j][1]));
                mx1 = fmaxf(mx1, fmaxf(s[j][2], s[j][3]));
            }
            mx0 = fmaxf(mx0, __shfl_xor_sync(0xffffffffu, mx0, 1));
            mx0 = fmaxf(mx0, __shfl_xor_sync(0xffffffffu, mx0, 2));
            mx1 = fmaxf(mx1, __shfl_xor_sync(0xffffffffu, mx1, 1));
            mx1 = fmaxf(mx1, __shfl_xor_sync(0xffffffffu, mx1, 2));

            const float mn0 = fmaxf(m_run0, mx0);
            const float mn1 = fmaxf(m_run1, mx1);
            const float c0 = ex2f(m_run0 - mn0);
            const float c1 = ex2f(m_run1 - mn1);
            m_run0 = mn0; m_run1 = mn1;
#pragma unroll
            for (int n = 0; n < 3; ++n) {
                o[n][0] *= c0; o[n][1] *= c0;
                o[n][2] *= c1; o[n][3] *= c1;
            }
            // ---- exp ----
#pragma unroll
            for (int j = 0; j < 8; ++j) {
                s[j][0] = ex2f(s[j][0] - mn0);
                s[j][1] = ex2f(s[j][1] - mn0);
                s[j][2] = ex2f(s[j][2] - mn1);
                s[j][3] = ex2f(s[j][3] - mn1);
            }
            // ---- PV (+ ones column for l): O += P·[V|1] ----
#pragma unroll
            for (int cc = 0; cc < 2; ++cc) {
                const int cp = 2 * hf + cc;
                uint32_t vh0[4], vh1[4], vh2[4];
                const uint32_t va = vAddr + (uint32_t)(cp * 64);
                ldmx4(vh0, va);
                ldmx4(vh1, va + 8 * VSTRIDE * 4);
                ldmx4(vh2, va + 16 * VSTRIDE * 4);
#pragma unroll
                for (int q2 = 0; q2 < 2; ++q2) {
                    const int c = 2 * cc + q2;
                    uint32_t a[4] = {
                        packh2(s[2 * c][0],     s[2 * c][1]),
                        packh2(s[2 * c][2],     s[2 * c][3]),
                        packh2(s[2 * c + 1][0], s[2 * c + 1][1]),
                        packh2(s[2 * c + 1][2], s[2 * c + 1][3])};
                    mma16816(o[0], a, vh0 + 2 * q2);
                    mma16816(o[1], a, vh1 + 2 * q2);
                    mma16816(o[2], a, vh2 + 2 * q2);
                }
            }
        }
        __syncthreads();
    }

    // ---- epilogue: l lives in col 16 (m4==0 lane of each quad) ----
    const float l0 = __shfl_sync(0xffffffffu, o[2][0], lane & ~3);
    const float l1 = __shfl_sync(0xffffffffu, o[2][2], lane & ~3);
    const float i0 = 1.f / l0, i1 = 1.f / l1;
    const int r0 = qt * 128 + warp * 16 + g;
#pragma unroll
    for (int n = 0; n < 2; ++n) {
        const int dim = h * D_K + 8 * n + 2 * m4;
        float2 lo = {o[n][0] * i0, o[n][1] * i0};
        float2 hi = {o[n][2] * i1, o[n][3] * i1};
        *(float2*)&g_attn[((size_t)b * N_SEQ + r0) * D_MODEL + dim]     = lo;
        *(float2*)&g_attn[((size_t)b * N_SEQ + r0 + 8) * D_MODEL + dim] = hi;
    }
}

// ===================== Kernel 3: FC projection + transpose ==================
__global__ __launch_bounds__(256) void fc_proj_kernel(
    const float* __restrict__ Wfc, const float* __restrict__ bfc,
    float* __restrict__ out)
{
    __shared__ float As[32 * 68];
    __shared__ float Wt[32 * 132];

    const int b  = blockIdx.y;
    const int n0 = blockIdx.x * 64;
    const int tid = threadIdx.x;
    const int tx = tid & 15, ty = tid >> 4;

    ull c2[4][4];
#pragma unroll
    for (int mm = 0; mm < 4; ++mm)
#pragma unroll
        for (int jp = 0; jp < 4; ++jp) c2[mm][jp] = 0ULL;

#pragma unroll 1
    for (int kc = 0; kc < 4; ++kc) {
        __syncthreads();
#pragma unroll
        for (int it = 0; it < 8; ++it) {
            int i = tid + it * 256;
            int m = i >> 5, dd = i & 31;
            As[dd * 68 + m] = g_attn[((size_t)b * N_SEQ + n0 + m) * D_MODEL + kc * 32 + dd];
        }
#pragma unroll
        for (int it = 0; it < 16; ++it) {
            int i = tid + it * 256;
            int j = i >> 5, dd = i & 31;
            Wt[dd * 132 + j] = Wfc[j * D_MODEL + kc * 32 + dd];
        }
        __syncthreads();

#pragma unroll 8
        for (int d = 0; d < 32; ++d) {
            float4 xv = *(const float4*)&As[d * 68 + tx * 4];
            ulonglong2 wA = *(const ulonglong2*)&Wt[d * 132 + ty * 8];
            ulonglong2 wB = *(const ulonglong2*)&Wt[d * 132 + ty * 8 + 4];
            ull x2[4] = {pack2(xv.x, xv.x), pack2(xv.y, xv.y),
                         pack2(xv.z, xv.z), pack2(xv.w, xv.w)};
#pragma unroll
            for (int mm = 0; mm < 4; ++mm) {
                c2[mm][0] = ffma2(x2[mm], wA.x, c2[mm][0]);
                c2[mm][1] = ffma2(x2[mm], wA.y, c2[mm][1]);
                c2[mm][2] = ffma2(x2[mm], wB.x, c2[mm][2]);
                c2[mm][3] = ffma2(x2[mm], wB.y, c2[mm][3]);
            }
        }
    }

    float cv[4][8];
#pragma unroll
    for (int mm = 0; mm < 4; ++mm)
#pragma unroll
        for (int jp = 0; jp < 4; ++jp) {
            float2 p = unpk2(c2[mm][jp]);
            cv[mm][2 * jp] = p.x; cv[mm][2 * jp + 1] = p.y;
        }

#pragma unroll
    for (int jj = 0; jj < 8; ++jj) {
        const int j = ty * 8 + jj;
        const float bias = bfc[j];
        float4 o = {cv[0][jj] + bias, cv[1][jj] + bias,
                    cv[2][jj] + bias, cv[3][jj] + bias};
        *(float4*)&out[((size_t)b * D_MODEL + j) * N_SEQ + n0 + tx * 4] = o;
    }
}

// ===========================================================================
extern "C" void kernel_launch(void* const* d_in, const int* in_sizes, int n_in,
                              void* d_out, int out_size)
{
    const float* x    = (const float*)d_in[0];
    const float* mask = (const float*)d_in[1];
    const float* Wq   = (const float*)d_in[2];
    const float* bq   = (const float*)d_in[3];
    const float* Wk   = (const float*)d_in[4];
    const float* bk   = (const float*)d_in[5];
    const float* Wv   = (const float*)d_in[6];
    const float* bv   = (const float*)d_in[7];
    const float* Wfc  = (const float*)d_in[8];
    const float* bfc  = (const float*)d_in[9];
    float* out = (float*)d_out;

    qkv_proj_kernel<<<dim3(N_SEQ / 64, BATCH, 3), 256>>>(x, Wq, bq, Wk, bk, Wv, bv);
    flash_attn_mma_kernel<<<dim3(N_SEQ / 128, N_HEAD, BATCH), 256>>>(mask);
    fc_proj_kernel<<<dim3(N_SEQ / 64, BATCH), 256>>>(Wfc, bfc, out);
}

// round 12
// speedup vs baseline: 4.4581x; 1.1510x over previous
#include <cuda_runtime.h>
#include <cuda_fp16.h>
#include <cstdint>

#define D_MODEL 128
#define N_SEQ   2048
#define BATCH   4
#define N_HEAD  8
#define D_K     16
#define NEG_INF -1e30f
#define LOG2E   1.4426950408889634f
#define QSCALE  (0.08838834764831843f * LOG2E)

typedef unsigned long long ull;
typedef unsigned short u16;

// ===================== helpers ==============================================
__device__ __forceinline__ float ex2f(float x) {
    float y; asm("ex2.approx.f32 %0, %1;" : "=f"(y) : "f"(x)); return y;
}
// pack two f32 into fp16x2 (a -> low half, b -> high half)
__device__ __forceinline__ uint32_t packh2(float a, float b) {
    uint32_t r; asm("cvt.rn.f16x2.f32 %0, %1, %2;" : "=r"(r) : "f"(b), "f"(a)); return r;
}
// split a float pair into fp16x2 hi + fp16x2 lo (lo = residual)
__device__ __forceinline__ void split_pair_h(float a, float b, uint32_t& hi, uint32_t& lo) {
    asm("cvt.rn.f16x2.f32 %0, %1, %2;" : "=r"(hi) : "f"(b), "f"(a));
    float ha, hb;
    asm("{.reg .b16 x,y; mov.b32 {x,y}, %2; cvt.f32.f16 %0, x; cvt.f32.f16 %1, y;}"
        : "=f"(ha), "=f"(hb) : "r"(hi));
    float ra = a - ha, rb = b - hb;
    asm("cvt.rn.f16x2.f32 %0, %1, %2;" : "=r"(lo) : "f"(rb), "f"(ra));
}
// mma.sync m16n8k16 fp16 (row.col), fp32 accum
__device__ __forceinline__ void mma16816(float* c, const uint32_t* a, const uint32_t* b) {
    asm volatile("mma.sync.aligned.m16n8k16.row.col.f32.f16.f16.f32 "
        "{%0,%1,%2,%3}, {%4,%5,%6,%7}, {%8,%9}, {%0,%1,%2,%3};"
        : "+f"(c[0]), "+f"(c[1]), "+f"(c[2]), "+f"(c[3])
        : "r"(a[0]), "r"(a[1]), "r"(a[2]), "r"(a[3]), "r"(b[0]), "r"(b[1]));
}
__device__ __forceinline__ void ldmx4(uint32_t* r, uint32_t addr) {
    asm volatile("ldmatrix.sync.aligned.m8n8.x4.shared.b16 {%0,%1,%2,%3}, [%4];"
        : "=r"(r[0]), "=r"(r[1]), "=r"(r[2]), "=r"(r[3]) : "r"(addr));
}
__device__ __forceinline__ uint32_t smem_u32(const void* p) {
    uint32_t a;
    asm("{ .reg .u64 t; cvta.to.shared.u64 t, %1; cvt.u32.u64 %0, t; }" : "=r"(a) : "l"(p));
    return a;
}

// ===================== scratch ==============================================
// fp16 tensors, head-blocked. Q/K: [bh][n][16]  V^T: [bh][16][N]
__device__ u16 g_qh[32 * N_SEQ * 16];
__device__ u16 g_khi[32 * N_SEQ * 16], g_klo[32 * N_SEQ * 16];
__device__ u16 g_vth[32 * 16 * N_SEQ];
__device__ float g_attn[BATCH * N_SEQ * D_MODEL];

// ===================== Kernel 1: QKV projection (mma.sync) ==================
// out[n,j] = sum_d X[n,d]*W[j,d] + b[j];  X from x:(B,D,N) (d-major).
// CTA: 128n x 128j, 512 threads = 16 warps; warp = (m16 tile, j-half).
// X staged raw fp32 [d][n]; A-frags via LDS pairs + split. W staged split fp16.
#define XSTR 132           // fp32 per d-row (pad)
#define WSTR 68            // u32 per j-row (136 fp16, pad)
#define QKV_SMEM (128 * XSTR * 4 + 2 * 128 * WSTR * 4)   // 137216 B

__global__ __launch_bounds__(512) void qkv_proj_kernel(
    const float* __restrict__ x,
    const float* __restrict__ Wq, const float* __restrict__ bq,
    const float* __restrict__ Wk, const float* __restrict__ bk,
    const float* __restrict__ Wv, const float* __restrict__ bv)
{
    extern __shared__ __align__(16) uint32_t dsm[];
    float*    Xs  = (float*)dsm;                 // [128][XSTR]
    uint32_t* Whi = dsm + 128 * XSTR;            // [128][WSTR]
    uint32_t* Wlo = Whi + 128 * WSTR;

    const int b  = blockIdx.y;
    const int n0 = blockIdx.x * 128;
    const int w  = blockIdx.z;
    const float* W    = (w == 0) ? Wq : (w == 1) ? Wk : Wv;
    const float* bias = (w == 0) ? bq : (w == 1) ? bk : bv;

    const int tid  = threadIdx.x;
    const int warp = tid >> 5, lane = tid & 31;
    const int g = lane >> 2, m4 = lane & 3;
    const int mt = warp >> 1;     // m-tile: n rows mt*16..+15
    const int jh = warp & 1;      // j-half: j0 = jh*64
    const int mat = lane >> 3, rin = lane & 7;

    // stage X fp32 [d][n]
#pragma unroll
    for (int it = 0; it < 8; ++it) {
        int i = tid + it * 512;           // float4 units, 4096 total
        int d = i >> 5, nn = (i & 31) * 4;
        *(float4*)&Xs[d * XSTR + nn] =
            *(const float4*)&x[((size_t)b * D_MODEL + d) * N_SEQ + n0 + nn];
    }
    // stage W split fp16 [j][d]
#pragma unroll
    for (int it = 0; it < 8; ++it) {
        int i = tid + it * 512;
        int j = i >> 5, dd = (i & 31) * 4;
        float4 wv = *(const float4*)&W[j * D_MODEL + dd];
        uint32_t h0, l0, h1, l1;
        split_pair_h(wv.x, wv.y, h0, l0);
        split_pair_h(wv.z, wv.w, h1, l1);
        Whi[j * WSTR + (dd >> 1)]     = h0;
        Whi[j * WSTR + (dd >> 1) + 1] = h1;
        Wlo[j * WSTR + (dd >> 1)]     = l0;
        Wlo[j * WSTR + (dd >> 1) + 1] = l1;
    }
    __syncthreads();

    const uint32_t wOff = (uint32_t)(((((mat >> 1) * 8 + rin) + jh * 64) * WSTR + (mat & 1) * 4) * 4);
    const uint32_t wAddrHi = smem_u32(Whi) + wOff;
    const uint32_t wAddrLo = smem_u32(Wlo) + wOff;

    float c[8][4];
#pragma unroll
    for (int jt = 0; jt < 8; ++jt)
#pragma unroll
        for (int i = 0; i < 4; ++i) c[jt][i] = 0.f;

    const int nr = mt * 16 + g;
#pragma unroll
    for (int ks = 0; ks < 8; ++ks) {
        const int d0 = ks * 16 + 2 * m4;
        uint32_t ah[4], al[4];
        split_pair_h(Xs[d0 * XSTR + nr],           Xs[(d0 + 1) * XSTR + nr],     ah[0], al[0]);
        split_pair_h(Xs[d0 * XSTR + nr + 8],       Xs[(d0 + 1) * XSTR + nr + 8], ah[1], al[1]);
        split_pair_h(Xs[(d0 + 8) * XSTR + nr],     Xs[(d0 + 9) * XSTR + nr],     ah[2], al[2]);
        split_pair_h(Xs[(d0 + 8) * XSTR + nr + 8], Xs[(d0 + 9) * XSTR + nr + 8], ah[3], al[3]);
#pragma unroll
        for (int jp = 0; jp < 4; ++jp) {
            uint32_t bh4[4], bl4[4];
            const uint32_t off = (uint32_t)((jp * 16 * WSTR + ks * 8) * 4);
            ldmx4(bh4, wAddrHi + off);
            ldmx4(bl4, wAddrLo + off);
#pragma unroll
            for (int q2 = 0; q2 < 2; ++q2) {
                float* cj = c[jp * 2 + q2];
                mma16816(cj, ah, bh4 + 2 * q2);
                mma16816(cj, ah, bl4 + 2 * q2);
                mma16816(cj, al, bh4 + 2 * q2);
            }
        }
    }

    // ---- epilogue: write directly into attention layouts ----
    const int nglob = n0 + nr;
#pragma unroll
    for (int jt = 0; jt < 8; ++jt) {
        const int j = jh * 64 + jt * 8 + 2 * m4;
        const float2 bj = *(const float2*)&bias[j];
        const int head = j >> 4, dim = j & 15;
        const int bh_ = b * N_HEAD + head;
        float v0 = c[jt][0] + bj.x, v1 = c[jt][1] + bj.y;   // row nglob
        float v2 = c[jt][2] + bj.x, v3 = c[jt][3] + bj.y;   // row nglob+8
        if (w == 0) {
            uint32_t p0 = packh2(v0 * QSCALE, v1 * QSCALE);
            uint32_t p1 = packh2(v2 * QSCALE, v3 * QSCALE);
            *(uint32_t*)&g_qh[((size_t)bh_ * N_SEQ + nglob) * 16 + dim]     = p0;
            *(uint32_t*)&g_qh[((size_t)bh_ * N_SEQ + nglob + 8) * 16 + dim] = p1;
        } else if (w == 1) {
            uint32_t h0, l0, h1, l1;
            split_pair_h(v0, v1, h0, l0);
            split_pair_h(v2, v3, h1, l1);
            *(uint32_t*)&g_khi[((size_t)bh_ * N_SEQ + nglob) * 16 + dim]     = h0;
            *(uint32_t*)&g_klo[((size_t)bh_ * N_SEQ + nglob) * 16 + dim]     = l0;
            *(uint32_t*)&g_khi[((size_t)bh_ * N_SEQ + nglob + 8) * 16 + dim] = h1;
            *(uint32_t*)&g_klo[((size_t)bh_ * N_SEQ + nglob + 8) * 16 + dim] = l1;
        } else {
            uint32_t p0 = packh2(v0, v1), p1 = packh2(v2, v3);
            const size_t r0 = ((size_t)bh_ * 16 + dim) * N_SEQ;
            const size_t r1 = ((size_t)bh_ * 16 + dim + 1) * N_SEQ;
            g_vth[r0 + nglob]     = (u16)(p0 & 0xffff);
            g_vth[r1 + nglob]     = (u16)(p0 >> 16);
            g_vth[r0 + nglob + 8] = (u16)(p1 & 0xffff);
            g_vth[r1 + nglob + 8] = (u16)(p1 >> 16);
        }
    }
}

// ===================== Kernel 2: mma.sync flash attention (unchanged) =======
#define KSTRIDE 12
#define VSTRIDE 68

__global__ __launch_bounds__(256, 2) void flash_attn_mma_kernel(
    const float* __restrict__ mask)
{
    __shared__ __align__(16) uint32_t Khi_s[128 * KSTRIDE], Klo_s[128 * KSTRIDE];
    __shared__ __align__(16) uint32_t Vth_s[24 * VSTRIDE];
    __shared__ float sb[128];

    const int qt = blockIdx.x, h = blockIdx.y, b = blockIdx.z;
    const int bh = b * N_HEAD + h;
    const int tid  = threadIdx.x;
    const int warp = tid >> 5;
    const int lane = tid & 31;
    const int g  = lane >> 2;
    const int m4 = lane & 3;
    const int mat = lane >> 3, rin = lane & 7;

    uint32_t aQ[4];
    {
        const uint32_t* qh = (const uint32_t*)g_qh + (size_t)bh * N_SEQ * 8;
        const int r0 = qt * 128 + warp * 16 + g, r1 = r0 + 8;
        aQ[0] = qh[r0 * 8 + m4];     aQ[1] = qh[r1 * 8 + m4];
        aQ[2] = qh[r0 * 8 + 4 + m4]; aQ[3] = qh[r1 * 8 + 4 + m4];
    }

    const uint32_t koff = (uint32_t)((((mat >> 1) * 8 + rin) * KSTRIDE + (mat & 1) * 4) * 4);
    const uint32_t kAddrHi = smem_u32(Khi_s) + koff;
    const uint32_t kAddrLo = smem_u32(Klo_s) + koff;
    const uint32_t voff = (uint32_t)(rin * VSTRIDE * 4 + mat * 16);
    const uint32_t vAddr = smem_u32(Vth_s) + voff;

    for (int i = tid; i < 8 * VSTRIDE; i += 256) {
        int r = i / VSTRIDE;
        Vth_s[(16 + r) * VSTRIDE + (i % VSTRIDE)] = (r == 0) ? 0x3C003C00u : 0u;
    }

    float o[3][4];
#pragma unroll
    for (int n = 0; n < 3; ++n)
#pragma unroll
        for (int i = 0; i < 4; ++i) o[n][i] = 0.f;
    float m_run0 = -1e30f, m_run1 = -1e30f;

#pragma unroll 1
    for (int t = 0; t < 16; ++t) {
        int pred = 0;
        if (tid < 128) {
            const size_t rb = ((size_t)bh * N_SEQ + t * 128 + tid) * 16;
            const uint4* kh = (const uint4*)&g_khi[rb];
            const uint4* kl = (const uint4*)&g_klo[rb];
            uint4 h0 = kh[0], h1 = kh[1], l0 = kl[0], l1 = kl[1];
            *(uint4*)&Khi_s[tid * KSTRIDE]     = h0;
            *(uint4*)&Khi_s[tid * KSTRIDE + 4] = h1;
            *(uint4*)&Klo_s[tid * KSTRIDE]     = l0;
            *(uint4*)&Klo_s[tid * KSTRIDE + 4] = l1;
            float mv = mask[(size_t)b * N_SEQ + t * 128 + tid];
            float bias = (1.f - mv) * (NEG_INF * LOG2E);
            sb[tid] = bias;
            pred = (bias != 0.f);
        } else {
            const int t2 = tid - 128;
            const int row = t2 >> 3, seg = t2 & 7;
            const size_t sbase = ((size_t)bh * 16 + row) * N_SEQ + t * 128 + seg * 16;
            const uint4* vh = (const uint4*)&g_vth[sbase];
            uint4 h0 = vh[0], h1 = vh[1];
            *(uint4*)&Vth_s[row * VSTRIDE + seg * 8]     = h0;
            *(uint4*)&Vth_s[row * VSTRIDE + seg * 8 + 4] = h1;
        }
        const int any_mask = __syncthreads_or(pred);

#pragma unroll
        for (int hf = 0; hf < 2; ++hf) {
            float s[8][4];
            uint32_t kh = kAddrHi + (uint32_t)(hf * 64 * KSTRIDE * 4);
            uint32_t kl = kAddrLo + (uint32_t)(hf * 64 * KSTRIDE * 4);
#pragma unroll
            for (int i = 0; i < 4; ++i) {
                uint32_t bh4[4], bl4[4];
                ldmx4(bh4, kh); ldmx4(bl4, kl);
                kh += 16 * KSTRIDE * 4; kl += 16 * KSTRIDE * 4;
#pragma unroll
                for (int q2 = 0; q2 < 2; ++q2) {
                    float* sj = s[2 * i + q2];
                    sj[0] = sj[1] = sj[2] = sj[3] = 0.f;
                    mma16816(sj, aQ, bh4 + 2 * q2);
                    mma16816(sj, aQ, bl4 + 2 * q2);
                }
            }
            if (any_mask) {
#pragma unroll
                for (int j = 0; j < 8; ++j) {
                    float2 sv = *(const float2*)&sb[hf * 64 + 8 * j + 2 * m4];
                    s[j][0] += sv.x; s[j][1] += sv.y;
                    s[j][2] += sv.x; s[j][3] += sv.y;
                }
            }
            float mx0 = fmaxf(s[0][0], s[0][1]), mx1 = fmaxf(s[0][2], s[0][3]);
#pragma unroll
            for (int j = 1; j < 8; ++j) {
                mx0 = fmaxf(mx0, fmaxf(s[j][0], s[j][1]));
                mx1 = fmaxf(mx1, fmaxf(s[j][2], s[j][3]));
            }
            mx0 = fmaxf(mx0, __shfl_xor_sync(0xffffffffu, mx0, 1));
            mx0 = fmaxf(mx0, __shfl_xor_sync(0xffffffffu, mx0, 2));
            mx1 = fmaxf(mx1, __shfl_xor_sync(0xffffffffu, mx1, 1));
            mx1 = fmaxf(mx1, __shfl_xor_sync(0xffffffffu, mx1, 2));

            const float mn0 = fmaxf(m_run0, mx0);
            const float mn1 = fmaxf(m_run1, mx1);
            const float c0 = ex2f(m_run0 - mn0);
            const float c1 = ex2f(m_run1 - mn1);
            m_run0 = mn0; m_run1 = mn1;
#pragma unroll
            for (int n = 0; n < 3; ++n) {
                o[n][0] *= c0; o[n][1] *= c0;
                o[n][2] *= c1; o[n][3] *= c1;
            }
#pragma unroll
            for (int j = 0; j < 8; ++j) {
                s[j][0] = ex2f(s[j][0] - mn0);
                s[j][1] = ex2f(s[j][1] - mn0);
                s[j][2] = ex2f(s[j][2] - mn1);
                s[j][3] = ex2f(s[j][3] - mn1);
            }
#pragma unroll
            for (int cc = 0; cc < 2; ++cc) {
                const int cp = 2 * hf + cc;
                uint32_t vh0[4], vh1[4], vh2[4];
                const uint32_t va = vAddr + (uint32_t)(cp * 64);
                ldmx4(vh0, va);
                ldmx4(vh1, va + 8 * VSTRIDE * 4);
                ldmx4(vh2, va + 16 * VSTRIDE * 4);
#pragma unroll
                for (int q2 = 0; q2 < 2; ++q2) {
                    const int c = 2 * cc + q2;
                    uint32_t a[4] = {
                        packh2(s[2 * c][0],     s[2 * c][1]),
                        packh2(s[2 * c][2],     s[2 * c][3]),
                        packh2(s[2 * c + 1][0], s[2 * c + 1][1]),
                        packh2(s[2 * c + 1][2], s[2 * c + 1][3])};
                    mma16816(o[0], a, vh0 + 2 * q2);
                    mma16816(o[1], a, vh1 + 2 * q2);
                    mma16816(o[2], a, vh2 + 2 * q2);
                }
            }
        }
        __syncthreads();
    }

    const float l0 = __shfl_sync(0xffffffffu, o[2][0], lane & ~3);
    const float l1 = __shfl_sync(0xffffffffu, o[2][2], lane & ~3);
    const float i0 = 1.f / l0, i1 = 1.f / l1;
    const int r0 = qt * 128 + warp * 16 + g;
#pragma unroll
    for (int n = 0; n < 2; ++n) {
        const int dim = h * D_K + 8 * n + 2 * m4;
        float2 lo = {o[n][0] * i0, o[n][1] * i0};
        float2 hi = {o[n][2] * i1, o[n][3] * i1};
        *(float2*)&g_attn[((size_t)b * N_SEQ + r0) * D_MODEL + dim]     = lo;
        *(float2*)&g_attn[((size_t)b * N_SEQ + r0 + 8) * D_MODEL + dim] = hi;
    }
}

// ===================== Kernel 3: FC projection (mma.sync) ===================
// out[b,j,n] = sum_d attn[b,n,d]*Wfc[j,d] + bfc[j].  CTA: 64n x 128j, 256 thr.
#define ASTR 68
#define FC_SMEM (2 * 64 * ASTR * 4 + 2 * 128 * WSTR * 4)   // 34816 + 69632 = 104448

__global__ __launch_bounds__(256) void fc_proj_kernel(
    const float* __restrict__ Wfc, const float* __restrict__ bfc,
    float* __restrict__ out)
{
    extern __shared__ __align__(16) uint32_t dsm[];
    uint32_t* Ahi = dsm;                       // [64][ASTR]
    uint32_t* Alo = Ahi + 64 * ASTR;
    uint32_t* Whi = Alo + 64 * ASTR;           // [128][WSTR]
    uint32_t* Wlo = Whi + 128 * WSTR;

    const int b  = blockIdx.y;
    const int n0 = blockIdx.x * 64;
    const int tid  = threadIdx.x;
    const int warp = tid >> 5, lane = tid & 31;
    const int g = lane >> 2, m4 = lane & 3;
    const int mt = warp >> 1;     // m-tile: n rows mt*16..+15
    const int jh = warp & 1;      // j-half
    const int mat = lane >> 3, rin = lane & 7;

    // stage A (attn) split fp16 [n][d]
#pragma unroll
    for (int it = 0; it < 8; ++it) {
        int i = tid + it * 256;           // 2048 float4 units
        int n = i >> 5, dd = (i & 31) * 4;
        float4 av = *(const float4*)&g_attn[((size_t)b * N_SEQ + n0 + n) * D_MODEL + dd];
        uint32_t h0, l0, h1, l1;
        split_pair_h(av.x, av.y, h0, l0);
        split_pair_h(av.z, av.w, h1, l1);
        Ahi[n * ASTR + (dd >> 1)]     = h0;
        Ahi[n * ASTR + (dd >> 1) + 1] = h1;
        Alo[n * ASTR + (dd >> 1)]     = l0;
        Alo[n * ASTR + (dd >> 1) + 1] = l1;
    }
    // stage W split fp16 [j][d]
#pragma unroll
    for (int it = 0; it < 16; ++it) {
        int i = tid + it * 256;           // 4096 float4 units
        int j = i >> 5, dd = (i & 31) * 4;
        float4 wv = *(const float4*)&Wfc[j * D_MODEL + dd];
        uint32_t h0, l0, h1, l1;
        split_pair_h(wv.x, wv.y, h0, l0);
        split_pair_h(wv.z, wv.w, h1, l1);
        Whi[j * WSTR + (dd >> 1)]     = h0;
        Whi[j * WSTR + (dd >> 1) + 1] = h1;
        Wlo[j * WSTR + (dd >> 1)]     = l0;
        Wlo[j * WSTR + (dd >> 1) + 1] = l1;
    }
    __syncthreads();

    const uint32_t aOff = (uint32_t)(((((mat >> 1) * 8 + rin) + mt * 16) * ASTR + (mat & 1) * 4) * 4);
    const uint32_t aAddrHi = smem_u32(Ahi) + aOff;
    const uint32_t aAddrLo = smem_u32(Alo) + aOff;
    const uint32_t wOff = (uint32_t)(((((mat >> 1) * 8 + rin) + jh * 64) * WSTR + (mat & 1) * 4) * 4);
    const uint32_t wAddrHi = smem_u32(Whi) + wOff;
    const uint32_t wAddrLo = smem_u32(Wlo) + wOff;

    float c[8][4];
#pragma unroll
    for (int jt = 0; jt < 8; ++jt)
#pragma unroll
        for (int i = 0; i < 4; ++i) c[jt][i] = 0.f;

#pragma unroll
    for (int ks = 0; ks < 8; ++ks) {
        uint32_t mh[4], ml[4];
        ldmx4(mh, aAddrHi + (uint32_t)(ks * 32));
        ldmx4(ml, aAddrLo + (uint32_t)(ks * 32));
        uint32_t ah[4] = {mh[0], mh[2], mh[1], mh[3]};   // ldmatrix mats -> a-frag order
        uint32_t al[4] = {ml[0], ml[2], ml[1], ml[3]};
#pragma unroll
        for (int jp = 0; jp < 4; ++jp) {
            uint32_t bh4[4], bl4[4];
            const uint32_t off = (uint32_t)((jp * 16 * WSTR + ks * 8) * 4);
            ldmx4(bh4, wAddrHi + off);
            ldmx4(bl4, wAddrLo + off);
#pragma unroll
            for (int q2 = 0; q2 < 2; ++q2) {
                float* cj = c[jp * 2 + q2];
                mma16816(cj, ah, bh4 + 2 * q2);
                mma16816(cj, ah, bl4 + 2 * q2);
                mma16816(cj, al, bh4 + 2 * q2);
            }
        }
    }

    // ---- epilogue: out (B, D, N) transposed scatter ----
    const int nglob = n0 + mt * 16 + g;
#pragma unroll
    for (int jt = 0; jt < 8; ++jt) {
        const int j = jh * 64 + jt * 8 + 2 * m4;
        const float2 bj = *(const float2*)&bfc[j];
        float* o0 = &out[((size_t)b * D_MODEL + j) * N_SEQ];
        float* o1 = &out[((size_t)b * D_MODEL + j + 1) * N_SEQ];
        o0[nglob]     = c[jt][0] + bj.x;
        o1[nglob]     = c[jt][1] + bj.y;
        o0[nglob + 8] = c[jt][2] + bj.x;
        o1[nglob + 8] = c[jt][3] + bj.y;
    }
}

// ===========================================================================
extern "C" void kernel_launch(void* const* d_in, const int* in_sizes, int n_in,
                              void* d_out, int out_size)
{
    const float* x    = (const float*)d_in[0];
    const float* mask = (const float*)d_in[1];
    const float* Wq   = (const float*)d_in[2];
    const float* bq   = (const float*)d_in[3];
    const float* Wk   = (const float*)d_in[4];
    const float* bk   = (const float*)d_in[5];
    const float* Wv   = (const float*)d_in[6];
    const float* bv   = (const float*)d_in[7];
    const float* Wfc  = (const float*)d_in[8];
    const float* bfc  = (const float*)d_in[9];
    float* out = (float*)d_out;

    cudaFuncSetAttribute(qkv_proj_kernel, cudaFuncAttributeMaxDynamicSharedMemorySize, QKV_SMEM);
    cudaFuncSetAttribute(fc_proj_kernel,  cudaFuncAttributeMaxDynamicSharedMemorySize, FC_SMEM);

    qkv_proj_kernel<<<dim3(N_SEQ / 128, BATCH, 3), 512, QKV_SMEM>>>(x, Wq, bq, Wk, bk, Wv, bv);
    flash_attn_mma_kernel<<<dim3(N_SEQ / 128, N_HEAD, BATCH), 256>>>(mask);
    fc_proj_kernel<<<dim3(N_SEQ / 64, BATCH), 256, FC_SMEM>>>(Wfc, bfc, out);
}